// round 2
// baseline (speedup 1.0000x reference)
#include <cuda_runtime.h>
#include <math.h>

// ---------------- problem constants ----------------
#define SEQ   1024
#define HDIM  2048
#define NH    16
#define KVH   8
#define HD    128
#define QKH   24          // NH + KVH
#define QKVO  4096        // (QKH+KVH)*HD
#define DFF   6144
#define VOC   32000
#define NLAY  2

// ---------------- scratch (device globals; no allocs allowed) ----------------
__device__ float g_x    [SEQ * HDIM];
__device__ float g_hn   [SEQ * HDIM];
__device__ float g_qkv  [SEQ * QKVO];
__device__ float g_q    [NH  * SEQ * HD];
__device__ float g_k    [KVH * SEQ * HD];
__device__ float g_vt   [KVH * HD * SEQ];     // V transposed: [kvh][d][s]
__device__ float g_sc   [NH * SEQ * SEQ];     // attention scores / probs
__device__ float g_ao   [SEQ * HDIM];         // attention output (S, NH*HD)
__device__ float g_gu   [SEQ * 2 * DFF];
__device__ float g_act  [SEQ * DFF];
__device__ float g_last [HDIM];

// ---------------- generic NT SGEMM: C[z] = A[z](MxK) * B[z>>shift](NxK)^T (+resid) ----
// Tiles: 128x128x16, 256 threads, 8x8 per thread. All M,N multiples of 128, K of 16.
__global__ __launch_bounds__(256) void sgemm_nt(
    const float* __restrict__ A, int lda,
    const float* __restrict__ B, int ldb,
    float* __restrict__ C, int ldc,
    int K,
    const float* __restrict__ resid, int ldr,
    long long bsA, long long bsB, long long bsC, int bShiftB)
{
    const long long z = blockIdx.z;
    A += z * bsA;
    B += (z >> bShiftB) * bsB;
    C += z * bsC;

    __shared__ __align__(16) float As[16][132];
    __shared__ __align__(16) float Bs[16][132];

    const int m0 = blockIdx.y * 128;
    const int n0 = blockIdx.x * 128;
    const int tid = threadIdx.x;
    const int ty = tid >> 4;      // 0..15
    const int tx = tid & 15;      // 0..15

    float acc[8][8];
#pragma unroll
    for (int i = 0; i < 8; i++)
#pragma unroll
        for (int j = 0; j < 8; j++) acc[i][j] = 0.f;

    for (int k0 = 0; k0 < K; k0 += 16) {
#pragma unroll
        for (int it = 0; it < 2; it++) {
            int v   = tid + it * 256;      // 0..511
            int row = v >> 2;              // 0..127
            int kq  = (v & 3) << 2;        // 0,4,8,12
            float4 av = *(const float4*)(A + (long long)(m0 + row) * lda + k0 + kq);
            As[kq + 0][row] = av.x; As[kq + 1][row] = av.y;
            As[kq + 2][row] = av.z; As[kq + 3][row] = av.w;
            float4 bv = *(const float4*)(B + (long long)(n0 + row) * ldb + k0 + kq);
            Bs[kq + 0][row] = bv.x; Bs[kq + 1][row] = bv.y;
            Bs[kq + 2][row] = bv.z; Bs[kq + 3][row] = bv.w;
        }
        __syncthreads();

#pragma unroll
        for (int kk = 0; kk < 16; kk++) {
            float4 a0 = *(const float4*)(&As[kk][ty * 8]);
            float4 a1 = *(const float4*)(&As[kk][ty * 8 + 4]);
            float4 b0 = *(const float4*)(&Bs[kk][tx * 8]);
            float4 b1 = *(const float4*)(&Bs[kk][tx * 8 + 4]);
            float a[8] = {a0.x, a0.y, a0.z, a0.w, a1.x, a1.y, a1.z, a1.w};
            float b[8] = {b0.x, b0.y, b0.z, b0.w, b1.x, b1.y, b1.z, b1.w};
#pragma unroll
            for (int i = 0; i < 8; i++)
#pragma unroll
                for (int j = 0; j < 8; j++)
                    acc[i][j] += a[i] * b[j];
        }
        __syncthreads();
    }

#pragma unroll
    for (int i = 0; i < 8; i++) {
        int m = m0 + ty * 8 + i;
#pragma unroll
        for (int j = 0; j < 8; j++) {
            int n = n0 + tx * 8 + j;
            float val = acc[i][j];
            if (resid) val += resid[(long long)m * ldr + n];
            C[(long long)m * ldc + n] = val;
        }
    }
}

// ---------------- row-wise l2norm: out = in * rsqrt(sum(in^2)) ----------------
__global__ void l2norm_rows(const float* __restrict__ in, float* __restrict__ out, int cols)
{
    const int row = blockIdx.x;
    const float* x = in + (long long)row * cols;
    float* y = out + (long long)row * cols;
    float s = 0.f;
    for (int c = threadIdx.x; c < cols; c += blockDim.x) { float v = x[c]; s += v * v; }
    __shared__ float red[32];
#pragma unroll
    for (int o = 16; o; o >>= 1) s += __shfl_xor_sync(0xffffffffu, s, o);
    if ((threadIdx.x & 31) == 0) red[threadIdx.x >> 5] = s;
    __syncthreads();
    const int nw = blockDim.x >> 5;
    if (threadIdx.x < 32) {
        float t = (threadIdx.x < nw) ? red[threadIdx.x] : 0.f;
#pragma unroll
        for (int o = 16; o; o >>= 1) t += __shfl_xor_sync(0xffffffffu, t, o);
        if (threadIdx.x == 0) red[0] = rsqrtf(t);
    }
    __syncthreads();
    const float r = red[0];
    for (int c = threadIdx.x; c < cols; c += blockDim.x) y[c] = x[c] * r;
}

// ---------------- per-head l2norm * qk_norm_w, then RoPE; scatter into Q/K ----------------
// grid: (SEQ, QKH), block: 128 (one thread per dim)
__global__ void qk_rope(const float* __restrict__ qkv, const float* __restrict__ qknw,
                        const float* __restrict__ cosb, const float* __restrict__ sinb,
                        float* __restrict__ Q, float* __restrict__ Kb)
{
    const int s = blockIdx.x;
    const int h = blockIdx.y;      // 0..23
    const int d = threadIdx.x;     // 0..127
    __shared__ float sv[128];
    __shared__ float red[4];

    float v = qkv[(long long)s * QKVO + h * HD + d];
    float ss = v * v;
#pragma unroll
    for (int o = 16; o; o >>= 1) ss += __shfl_xor_sync(0xffffffffu, ss, o);
    if ((d & 31) == 0) red[d >> 5] = ss;
    __syncthreads();
    const float tot = red[0] + red[1] + red[2] + red[3];
    const float nv = v * rsqrtf(tot) * qknw[h * HD + d];
    sv[d] = nv;
    __syncthreads();
    const float rot = (d < 64) ? sv[d + 64] : sv[d - 64];
    const float ov = nv * cosb[s * HD + d] + rot * sinb[s * HD + d];
    if (h < NH) Q[((long long)h * SEQ + s) * HD + d] = ov;
    else        Kb[((long long)(h - NH) * SEQ + s) * HD + d] = ov;
}

// ---------------- V transpose: qkv[s][3072 + h*128 + d] -> Vt[h][d][s] ----------------
__global__ void v_transpose(const float* __restrict__ qkv, float* __restrict__ Vt)
{
    __shared__ float t[32][33];
    const int h = blockIdx.z;
    const int s0 = blockIdx.x * 32;
    const int d0 = blockIdx.y * 32;
    const int s = s0 + threadIdx.y;
    const int d = d0 + threadIdx.x;
    t[threadIdx.y][threadIdx.x] = qkv[(long long)s * QKVO + QKH * HD + h * HD + d];
    __syncthreads();
    Vt[((long long)h * HD + d0 + threadIdx.y) * SEQ + s0 + threadIdx.x] = t[threadIdx.x][threadIdx.y];
}

// ---------------- causal softmax with additive -128*mask penalty ----------------
// grid: (SEQ, NH), block: 256; row length SEQ (4 per thread)
__global__ void softmax_causal(float* __restrict__ scores, const float* __restrict__ maskp)
{
    const int q = blockIdx.x;
    const int h = blockIdx.y;
    float* row = scores + ((long long)h * SEQ + q) * SEQ;
    const float mpen = -128.f * maskp[0];
    const int tid = threadIdx.x;

    float vals[4];
    float mx = -1e30f;
#pragma unroll
    for (int i = 0; i < 4; i++) {
        int k = tid + i * 256;
        float v = row[k] + (k > q ? mpen : 0.f);
        vals[i] = v;
        mx = fmaxf(mx, v);
    }
    __shared__ float redm[8];
    __shared__ float reds[8];
#pragma unroll
    for (int o = 16; o; o >>= 1) mx = fmaxf(mx, __shfl_xor_sync(0xffffffffu, mx, o));
    if ((tid & 31) == 0) redm[tid >> 5] = mx;
    __syncthreads();
    if (tid < 32) {
        float m2 = (tid < 8) ? redm[tid] : -1e30f;
#pragma unroll
        for (int o = 16; o; o >>= 1) m2 = fmaxf(m2, __shfl_xor_sync(0xffffffffu, m2, o));
        if (tid == 0) redm[0] = m2;
    }
    __syncthreads();
    mx = redm[0];

    float s = 0.f;
#pragma unroll
    for (int i = 0; i < 4; i++) { vals[i] = expf(vals[i] - mx); s += vals[i]; }
#pragma unroll
    for (int o = 16; o; o >>= 1) s += __shfl_xor_sync(0xffffffffu, s, o);
    if ((tid & 31) == 0) reds[tid >> 5] = s;
    __syncthreads();
    if (tid < 32) {
        float t2 = (tid < 8) ? reds[tid] : 0.f;
#pragma unroll
        for (int o = 16; o; o >>= 1) t2 += __shfl_xor_sync(0xffffffffu, t2, o);
        if (tid == 0) reds[0] = 1.f / t2;
    }
    __syncthreads();
    const float inv = reds[0];
#pragma unroll
    for (int i = 0; i < 4; i++) row[tid + i * 256] = vals[i] * inv;
}

// ---------------- SwiGLU: act = silu(gate) * up ----------------
__global__ void silu_mul(const float* __restrict__ gu, float* __restrict__ act)
{
    const long long i = (long long)blockIdx.x * blockDim.x + threadIdx.x;
    const int s = (int)(i / DFF);
    const int f = (int)(i % DFF);
    const float g = gu[(long long)s * (2 * DFF) + f];
    const float u = gu[(long long)s * (2 * DFF) + DFF + f];
    act[i] = (g / (1.f + expf(-g))) * u;
}

// ---------------- lm_head GEMV: out[v] = sum_h last[h]*W[v][h]; 1 warp / output ----------------
__global__ void lm_head(const float* __restrict__ last, const float* __restrict__ W,
                        float* __restrict__ out)
{
    const int warp = threadIdx.x >> 5;
    const int lane = threadIdx.x & 31;
    const int v = blockIdx.x * 8 + warp;
    const float* w = W + (long long)v * HDIM;
    float s = 0.f;
#pragma unroll
    for (int j = lane * 4; j < HDIM; j += 128) {
        float4 wv = *(const float4*)(w + j);
        float4 lv = *(const float4*)(last + j);
        s += wv.x * lv.x + wv.y * lv.y + wv.z * lv.z + wv.w * lv.w;
    }
#pragma unroll
    for (int o = 16; o; o >>= 1) s += __shfl_xor_sync(0xffffffffu, s, o);
    if (lane == 0) out[v] = s;
}

// ---------------- launcher ----------------
extern "C" void kernel_launch(void* const* d_in, const int* in_sizes, int n_in,
                              void* d_out, int out_size)
{
    const float* hidden = (const float*)d_in[0];
    const float* qkv_w  = (const float*)d_in[1];
    const float* qknw   = (const float*)d_in[2];
    const float* o_w    = (const float*)d_in[3];
    const float* gu_w   = (const float*)d_in[4];
    const float* dn_w   = (const float*)d_in[5];
    const float* lm_w   = (const float*)d_in[6];
    const float* cosb   = (const float*)d_in[7];
    const float* sinb   = (const float*)d_in[8];
    const float* maskp  = (const float*)d_in[9];
    float* outp = (float*)d_out;

    float *px, *phn, *pqkv, *pq, *pk, *pvt, *psc, *pao, *pgu, *pact, *plast;
    cudaGetSymbolAddress((void**)&px,    g_x);
    cudaGetSymbolAddress((void**)&phn,   g_hn);
    cudaGetSymbolAddress((void**)&pqkv,  g_qkv);
    cudaGetSymbolAddress((void**)&pq,    g_q);
    cudaGetSymbolAddress((void**)&pk,    g_k);
    cudaGetSymbolAddress((void**)&pvt,   g_vt);
    cudaGetSymbolAddress((void**)&psc,   g_sc);
    cudaGetSymbolAddress((void**)&pao,   g_ao);
    cudaGetSymbolAddress((void**)&pgu,   g_gu);
    cudaGetSymbolAddress((void**)&pact,  g_act);
    cudaGetSymbolAddress((void**)&plast, g_last);

    const float* xin = hidden;   // residual source for layer 0 attention block

    for (int l = 0; l < NLAY; l++) {
        // pre-attn l2norm
        l2norm_rows<<<SEQ, 256>>>(xin, phn, HDIM);

        // QKV projection: (S,H) x (4096,H)^T
        sgemm_nt<<<dim3(QKVO / 128, SEQ / 128, 1), 256>>>(
            phn, HDIM, qkv_w + (long long)l * QKVO * HDIM, HDIM,
            pqkv, QKVO, HDIM, nullptr, 0, 0, 0, 0, 0);

        // per-head norm + RoPE, V transpose
        qk_rope<<<dim3(SEQ, QKH), 128>>>(pqkv, qknw + (long long)l * QKH * HD, cosb, sinb, pq, pk);
        v_transpose<<<dim3(SEQ / 32, HD / 32, KVH), dim3(32, 32)>>>(pqkv, pvt);

        // scores[h] = Q[h] (S,HD) x K[h/2] (S,HD)^T
        sgemm_nt<<<dim3(SEQ / 128, SEQ / 128, NH), 256>>>(
            pq, HD, pk, HD, psc, SEQ, HD, nullptr, 0,
            (long long)SEQ * HD, (long long)SEQ * HD, (long long)SEQ * SEQ, 1);

        softmax_causal<<<dim3(SEQ, NH), 256>>>(psc, maskp);

        // out[h] = P[h] (S,S) x Vt[h/2] (HD,S)^T  -> pao[:, h*128:(h+1)*128]
        sgemm_nt<<<dim3(HD / 128, SEQ / 128, NH), 256>>>(
            psc, SEQ, pvt, SEQ, pao, HDIM, SEQ, nullptr, 0,
            (long long)SEQ * SEQ, (long long)HD * SEQ, (long long)HD, 1);

        // O projection + residual: x = resid + ao x o_w^T
        sgemm_nt<<<dim3(HDIM / 128, SEQ / 128, 1), 256>>>(
            pao, HDIM, o_w + (long long)l * HDIM * HDIM, HDIM,
            px, HDIM, HDIM, xin, HDIM, 0, 0, 0, 0);

        // MLP
        l2norm_rows<<<SEQ, 256>>>(px, phn, HDIM);
        sgemm_nt<<<dim3(2 * DFF / 128, SEQ / 128, 1), 256>>>(
            phn, HDIM, gu_w + (long long)l * 2 * DFF * HDIM, HDIM,
            pgu, 2 * DFF, HDIM, nullptr, 0, 0, 0, 0, 0);
        silu_mul<<<(SEQ * DFF) / 256, 256>>>(pgu, pact);
        sgemm_nt<<<dim3(HDIM / 128, SEQ / 128, 1), 256>>>(
            pact, DFF, dn_w + (long long)l * HDIM * DFF, DFF,
            px, HDIM, DFF, px, HDIM, 0, 0, 0, 0);

        xin = px;
    }

    // final: l2norm last token, lm_head
    l2norm_rows<<<1, 256>>>(px + (long long)(SEQ - 1) * HDIM, plast, HDIM);
    lm_head<<<VOC / 8, 256>>>(plast, lm_w, outp);
}

// round 4
// speedup vs baseline: 2.9125x; 2.9125x over previous
#include <cuda_runtime.h>
#include <cuda_bf16.h>
#include <stdint.h>
#include <math.h>

#define SEQ   1024
#define HDIM  2048
#define NH    16
#define KVH   8
#define HD    128
#define QKH   24
#define QKVO  4096
#define DFF   6144
#define VOC   32000
#define NLAY  2

typedef __nv_bfloat16 bf16;

// ---------------- device scratch (no allocs allowed) ----------------
__device__ __align__(16) float g_x   [SEQ*HDIM];
__device__ __align__(16) bf16  g_hnh [SEQ*HDIM];
__device__ __align__(16) bf16  g_hnl [SEQ*HDIM];
__device__ __align__(16) bf16  g_wh  [2*DFF*HDIM];
__device__ __align__(16) bf16  g_wl  [2*DFF*HDIM];
__device__ __align__(16) float g_qkv [SEQ*QKVO];
__device__ __align__(16) bf16  g_qh  [NH*SEQ*HD];
__device__ __align__(16) bf16  g_ql  [NH*SEQ*HD];
__device__ __align__(16) bf16  g_kh  [KVH*SEQ*HD];
__device__ __align__(16) bf16  g_kl  [KVH*SEQ*HD];
__device__ __align__(16) bf16  g_vth [KVH*HD*SEQ];
__device__ __align__(16) bf16  g_vtl [KVH*HD*SEQ];
__device__ __align__(16) float g_sc  [NH*SEQ*SEQ];
__device__ __align__(16) bf16  g_ph  [NH*SEQ*SEQ];
__device__ __align__(16) bf16  g_pl  [NH*SEQ*SEQ];
__device__ __align__(16) bf16  g_paoh[SEQ*HDIM];
__device__ __align__(16) bf16  g_paol[SEQ*HDIM];
__device__ __align__(16) float g_gu  [SEQ*2*DFF];
__device__ __align__(16) bf16  g_acth[SEQ*DFF];
__device__ __align__(16) bf16  g_actl[SEQ*DFF];
__device__ __align__(16) float g_last[HDIM];

// ---------------- helpers ----------------
__device__ __forceinline__ uint32_t smem_u32(const void* p) {
    uint32_t a;
    asm("{ .reg .u64 t; cvta.to.shared.u64 t, %1; cvt.u32.u64 %0, t; }" : "=r"(a) : "l"(p));
    return a;
}
__device__ __forceinline__ uint32_t pack2(bf16 a, bf16 b) {
    return (uint32_t)__bfloat16_as_ushort(a) | ((uint32_t)__bfloat16_as_ushort(b) << 16);
}
__device__ __forceinline__ void split2(float x, bf16& h, bf16& l) {
    h = __float2bfloat16_rn(x);
    l = __float2bfloat16_rn(x - __bfloat162float(h));
}

#define CPA16(d, s) asm volatile("cp.async.cg.shared.global [%0], [%1], 16;" :: "r"(d), "l"(s))
#define CPA_COMMIT() asm volatile("cp.async.commit_group;" ::: "memory")
#define CPA_WAIT(n)  asm volatile("cp.async.wait_group %0;" :: "n"(n) : "memory")

#define LDSM4(r, a) \
    asm volatile("ldmatrix.sync.aligned.m8n8.x4.shared.b16 {%0,%1,%2,%3}, [%4];" \
        : "=r"((r)[0]), "=r"((r)[1]), "=r"((r)[2]), "=r"((r)[3]) : "r"(a))

#define MMA16816(c, a, b) \
    asm volatile("mma.sync.aligned.m16n8k16.row.col.f32.bf16.bf16.f32 " \
        "{%0,%1,%2,%3}, {%4,%5,%6,%7}, {%8,%9}, {%0,%1,%2,%3};" \
        : "+f"((c)[0]), "+f"((c)[1]), "+f"((c)[2]), "+f"((c)[3]) \
        : "r"((a)[0]), "r"((a)[1]), "r"((a)[2]), "r"((a)[3]), "r"((b)[0]), "r"((b)[1]))

// ============================================================================
// HMMA bf16 3-term-split GEMM (NT): C[z](128x128 tile) = A(MxK) * B(NxK)^T
// K in 64-chunks, 2-stage cp.async pipeline, swizzled 128B smem rows.
// Stage layout: [Ah 16K][Al 16K][Bh 16K][Bl 16K]; 2 stages = 128KB.
// ============================================================================
__global__ __launch_bounds__(256)
void hmma_gemm(const bf16* __restrict__ Ah, const bf16* __restrict__ Al, int lda,
               const bf16* __restrict__ Bh, const bf16* __restrict__ Bl, int ldb,
               float* __restrict__ C, int ldc, int K,
               const float* __restrict__ resid, int ldr,
               bf16* __restrict__ Chi, bf16* __restrict__ Clo,
               long long bsA, long long bsB, long long bsC, int bShiftB)
{
    constexpr int STAGE = 65536;
    extern __shared__ char dynraw[];
    char* sm = (char*)(((uintptr_t)dynraw + 1023) & ~(uintptr_t)1023);
    const uint32_t smb = smem_u32(sm);

    const int tid  = threadIdx.x;
    const int lane = tid & 31;
    const int wid  = tid >> 5;
    const int wm   = (wid >> 2) * 64;   // warp m offset in tile
    const int wn   = (wid & 3) * 32;    // warp n offset in tile

    const long long z = blockIdx.z;
    Ah += z * bsA;  Al += z * bsA;
    Bh += (z >> bShiftB) * bsB;  Bl += (z >> bShiftB) * bsB;
    if (C)   C   += z * bsC;
    if (Chi) { Chi += z * bsC; Clo += z * bsC; }

    const int m0 = blockIdx.y * 128;
    const int n0 = blockIdx.x * 128;

    // ldmatrix per-lane addressing components
    const int a_row_l  = lane & 15;          // A: lanes 0-15 rows, 16-31 repeat
    const int a_colq_l = lane >> 4;          // A: second half lanes take +8 k
    const int b_row_l  = (lane & 7) + ((lane & 16) >> 1);  // B: n-rows
    const int b_colq_l = (lane >> 3) & 1;    // B: lanes 8-15 take +8 k

    float acc[4][4][4];
#pragma unroll
    for (int i = 0; i < 4; i++)
#pragma unroll
        for (int j = 0; j < 4; j++)
#pragma unroll
            for (int q = 0; q < 4; q++) acc[i][j][q] = 0.f;

    auto load_chunk = [&](int c) {
        const int k0 = c << 6;
        const uint32_t st = smb + (c & 1) * STAGE;
#pragma unroll
        for (int it = 0; it < 16; it++) {
            const int g   = it * 256 + tid;
            const int arr = it >> 2;          // 0:Ah 1:Al 2:Bh 3:Bl
            const int r   = (g >> 3) & 127;
            const int q   = g & 7;
            const bf16* src;
            if      (arr == 0) src = Ah + (size_t)(m0 + r) * lda + k0 + q * 8;
            else if (arr == 1) src = Al + (size_t)(m0 + r) * lda + k0 + q * 8;
            else if (arr == 2) src = Bh + (size_t)(n0 + r) * ldb + k0 + q * 8;
            else               src = Bl + (size_t)(n0 + r) * ldb + k0 + q * 8;
            const uint32_t dst = st + arr * 16384 + r * 128 + ((q ^ (r & 7)) << 4);
            CPA16(dst, src);
        }
        CPA_COMMIT();
    };

    const int nch = K >> 6;
    load_chunk(0);

    for (int c = 0; c < nch; c++) {
        if (c + 1 < nch) { load_chunk(c + 1); CPA_WAIT(1); }
        else             { CPA_WAIT(0); }
        __syncthreads();

        const uint32_t st = smb + (c & 1) * STAGE;
        const uint32_t sAh = st, sAl = st + 16384, sBh = st + 32768, sBl = st + 49152;

#pragma unroll
        for (int kk = 0; kk < 4; kk++) {
            uint32_t ahf[4][4], alf[4][4], bhf[4][2], blf[4][2];
            const int acq = kk * 2 + a_colq_l;
#pragma unroll
            for (int mi = 0; mi < 4; mi++) {
                const int r = wm + mi * 16 + a_row_l;
                const uint32_t off = r * 128 + ((acq ^ (r & 7)) << 4);
                LDSM4(ahf[mi], sAh + off);
                LDSM4(alf[mi], sAl + off);
            }
            const int bcq = kk * 2 + b_colq_l;
#pragma unroll
            for (int nj = 0; nj < 2; nj++) {
                const int r = wn + nj * 16 + b_row_l;
                const uint32_t off = r * 128 + ((bcq ^ (r & 7)) << 4);
                uint32_t t4[4];
                LDSM4(t4, sBh + off);
                bhf[nj*2][0] = t4[0]; bhf[nj*2][1] = t4[1];
                bhf[nj*2+1][0] = t4[2]; bhf[nj*2+1][1] = t4[3];
                LDSM4(t4, sBl + off);
                blf[nj*2][0] = t4[0]; blf[nj*2][1] = t4[1];
                blf[nj*2+1][0] = t4[2]; blf[nj*2+1][1] = t4[3];
            }
#pragma unroll
            for (int mi = 0; mi < 4; mi++)
#pragma unroll
                for (int ni = 0; ni < 4; ni++) {
                    MMA16816(acc[mi][ni], ahf[mi], bhf[ni]);
                    MMA16816(acc[mi][ni], ahf[mi], blf[ni]);
                    MMA16816(acc[mi][ni], alf[mi], bhf[ni]);
                }
        }
        __syncthreads();
    }

    // ---- epilogue ----
    const int g = lane >> 2, t = lane & 3;
#pragma unroll
    for (int mi = 0; mi < 4; mi++)
#pragma unroll
        for (int ni = 0; ni < 4; ni++)
#pragma unroll
            for (int half = 0; half < 2; half++) {
                const int row = m0 + wm + mi * 16 + g + half * 8;
                const int col = n0 + wn + ni * 8 + 2 * t;
                float v0 = acc[mi][ni][half * 2 + 0];
                float v1 = acc[mi][ni][half * 2 + 1];
                if (resid) {
                    const float* rp = resid + (size_t)row * ldr + col;
                    v0 += rp[0]; v1 += rp[1];
                }
                if (C) *(float2*)(C + (size_t)row * ldc + col) = make_float2(v0, v1);
                if (Chi) {
                    bf16 h0, l0, h1, l1;
                    split2(v0, h0, l0); split2(v1, h1, l1);
                    *(uint32_t*)(Chi + (size_t)row * ldc + col) = pack2(h0, h1);
                    *(uint32_t*)(Clo + (size_t)row * ldc + col) = pack2(l0, l1);
                }
            }
}

// ---------------- fp32 -> (hi,lo) bf16 split, 4 elems/thread ----------------
__global__ void split4(const float4* __restrict__ in, uint2* __restrict__ hi,
                       uint2* __restrict__ lo, long long n4)
{
    long long i = (long long)blockIdx.x * blockDim.x + threadIdx.x;
    if (i >= n4) return;
    float4 v = in[i];
    bf16 h0, l0, h1, l1, h2, l2, h3, l3;
    split2(v.x, h0, l0); split2(v.y, h1, l1); split2(v.z, h2, l2); split2(v.w, h3, l3);
    hi[i] = make_uint2(pack2(h0, h1), pack2(h2, h3));
    lo[i] = make_uint2(pack2(l0, l1), pack2(l2, l3));
}

// ---------------- row l2norm -> split bf16 ----------------
__global__ void l2norm_rows_split(const float* __restrict__ in, bf16* __restrict__ hi,
                                  bf16* __restrict__ lo, int cols)
{
    const int row = blockIdx.x;
    const float* x = in + (long long)row * cols;
    float s = 0.f;
    for (int c = threadIdx.x; c < cols; c += blockDim.x) { float v = x[c]; s += v * v; }
    __shared__ float red[32];
#pragma unroll
    for (int o = 16; o; o >>= 1) s += __shfl_xor_sync(0xffffffffu, s, o);
    if ((threadIdx.x & 31) == 0) red[threadIdx.x >> 5] = s;
    __syncthreads();
    const int nw = blockDim.x >> 5;
    if (threadIdx.x < 32) {
        float t = (threadIdx.x < nw) ? red[threadIdx.x] : 0.f;
#pragma unroll
        for (int o = 16; o; o >>= 1) t += __shfl_xor_sync(0xffffffffu, t, o);
        if (threadIdx.x == 0) red[0] = rsqrtf(t);
    }
    __syncthreads();
    const float r = red[0];
    for (int c = threadIdx.x; c < cols; c += blockDim.x) {
        bf16 h, l;
        split2(x[c] * r, h, l);
        hi[(long long)row * cols + c] = h;
        lo[(long long)row * cols + c] = l;
    }
}

__global__ void l2norm_rows(const float* __restrict__ in, float* __restrict__ out, int cols)
{
    const int row = blockIdx.x;
    const float* x = in + (long long)row * cols;
    float* y = out + (long long)row * cols;
    float s = 0.f;
    for (int c = threadIdx.x; c < cols; c += blockDim.x) { float v = x[c]; s += v * v; }
    __shared__ float red[32];
#pragma unroll
    for (int o = 16; o; o >>= 1) s += __shfl_xor_sync(0xffffffffu, s, o);
    if ((threadIdx.x & 31) == 0) red[threadIdx.x >> 5] = s;
    __syncthreads();
    const int nw = blockDim.x >> 5;
    if (threadIdx.x < 32) {
        float t = (threadIdx.x < nw) ? red[threadIdx.x] : 0.f;
#pragma unroll
        for (int o = 16; o; o >>= 1) t += __shfl_xor_sync(0xffffffffu, t, o);
        if (threadIdx.x == 0) red[0] = rsqrtf(t);
    }
    __syncthreads();
    const float r = red[0];
    for (int c = threadIdx.x; c < cols; c += blockDim.x) y[c] = x[c] * r;
}

// ---------------- per-head norm + RoPE -> split Q/K ----------------
__global__ void qk_rope_split(const float* __restrict__ qkv, const float* __restrict__ qknw,
                              const float* __restrict__ cosb, const float* __restrict__ sinb,
                              bf16* __restrict__ Qh, bf16* __restrict__ Ql,
                              bf16* __restrict__ Kh, bf16* __restrict__ Kl)
{
    const int s = blockIdx.x;
    const int h = blockIdx.y;
    const int d = threadIdx.x;
    __shared__ float sv[128];
    __shared__ float red[4];

    float v = qkv[(long long)s * QKVO + h * HD + d];
    float ss = v * v;
#pragma unroll
    for (int o = 16; o; o >>= 1) ss += __shfl_xor_sync(0xffffffffu, ss, o);
    if ((d & 31) == 0) red[d >> 5] = ss;
    __syncthreads();
    const float tot = red[0] + red[1] + red[2] + red[3];
    const float nv = v * rsqrtf(tot) * qknw[h * HD + d];
    sv[d] = nv;
    __syncthreads();
    const float rot = (d < 64) ? sv[d + 64] : sv[d - 64];
    const float ov = nv * cosb[s * HD + d] + rot * sinb[s * HD + d];
    bf16 hh, ll;
    split2(ov, hh, ll);
    if (h < NH) {
        size_t o = ((size_t)h * SEQ + s) * HD + d;
        Qh[o] = hh; Ql[o] = ll;
    } else {
        size_t o = ((size_t)(h - NH) * SEQ + s) * HD + d;
        Kh[o] = hh; Kl[o] = ll;
    }
}

// ---------------- V transpose -> split ----------------
__global__ void v_transpose_split(const float* __restrict__ qkv,
                                  bf16* __restrict__ Vth, bf16* __restrict__ Vtl)
{
    __shared__ float t[32][33];
    const int h = blockIdx.z;
    const int s0 = blockIdx.x * 32;
    const int d0 = blockIdx.y * 32;
    t[threadIdx.y][threadIdx.x] =
        qkv[(long long)(s0 + threadIdx.y) * QKVO + QKH * HD + h * HD + d0 + threadIdx.x];
    __syncthreads();
    bf16 hh, ll;
    split2(t[threadIdx.x][threadIdx.y], hh, ll);
    size_t o = ((size_t)h * HD + d0 + threadIdx.y) * SEQ + s0 + threadIdx.x;
    Vth[o] = hh; Vtl[o] = ll;
}

// ---------------- causal softmax -> split probs ----------------
__global__ void softmax_causal_split(const float* __restrict__ scores, const float* __restrict__ maskp,
                                     bf16* __restrict__ Ph, bf16* __restrict__ Pl)
{
    const int q = blockIdx.x;
    const int h = blockIdx.y;
    const float* row = scores + ((long long)h * SEQ + q) * SEQ;
    const float mpen = -128.f * maskp[0];
    const int tid = threadIdx.x;

    float vals[4];
    float mx = -1e30f;
#pragma unroll
    for (int i = 0; i < 4; i++) {
        int k = tid + i * 256;
        float v = row[k] + (k > q ? mpen : 0.f);
        vals[i] = v;
        mx = fmaxf(mx, v);
    }
    __shared__ float redm[8];
    __shared__ float reds[8];
#pragma unroll
    for (int o = 16; o; o >>= 1) mx = fmaxf(mx, __shfl_xor_sync(0xffffffffu, mx, o));
    if ((tid & 31) == 0) redm[tid >> 5] = mx;
    __syncthreads();
    if (tid < 32) {
        float m2 = (tid < 8) ? redm[tid] : -1e30f;
#pragma unroll
        for (int o = 16; o; o >>= 1) m2 = fmaxf(m2, __shfl_xor_sync(0xffffffffu, m2, o));
        if (tid == 0) redm[0] = m2;
    }
    __syncthreads();
    mx = redm[0];

    float s = 0.f;
#pragma unroll
    for (int i = 0; i < 4; i++) { vals[i] = expf(vals[i] - mx); s += vals[i]; }
#pragma unroll
    for (int o = 16; o; o >>= 1) s += __shfl_xor_sync(0xffffffffu, s, o);
    if ((tid & 31) == 0) reds[tid >> 5] = s;
    __syncthreads();
    if (tid < 32) {
        float t2 = (tid < 8) ? reds[tid] : 0.f;
#pragma unroll
        for (int o = 16; o; o >>= 1) t2 += __shfl_xor_sync(0xffffffffu, t2, o);
        if (tid == 0) reds[0] = 1.f / t2;
    }
    __syncthreads();
    const float inv = reds[0];
    const size_t base = ((size_t)h * SEQ + q) * SEQ;
#pragma unroll
    for (int i = 0; i < 4; i++) {
        bf16 hh, ll;
        split2(vals[i] * inv, hh, ll);
        Ph[base + tid + i * 256] = hh;
        Pl[base + tid + i * 256] = ll;
    }
}

// ---------------- SwiGLU -> split ----------------
__global__ void silu_mul_split(const float* __restrict__ gu, bf16* __restrict__ Ah, bf16* __restrict__ Al)
{
    const long long i = (long long)blockIdx.x * blockDim.x + threadIdx.x;
    const int s = (int)(i / DFF);
    const int f = (int)(i % DFF);
    const float g = gu[(long long)s * (2 * DFF) + f];
    const float u = gu[(long long)s * (2 * DFF) + DFF + f];
    bf16 hh, ll;
    split2((g / (1.f + expf(-g))) * u, hh, ll);
    Ah[i] = hh; Al[i] = ll;
}

// ---------------- lm_head GEMV (fp32) ----------------
__global__ void lm_head(const float* __restrict__ last, const float* __restrict__ W,
                        float* __restrict__ out)
{
    const int warp = threadIdx.x >> 5;
    const int lane = threadIdx.x & 31;
    const int v = blockIdx.x * 8 + warp;
    const float* w = W + (long long)v * HDIM;
    float s = 0.f;
#pragma unroll
    for (int j = lane * 4; j < HDIM; j += 128) {
        float4 wv = *(const float4*)(w + j);
        float4 lv = *(const float4*)(last + j);
        s += wv.x * lv.x + wv.y * lv.y + wv.z * lv.z + wv.w * lv.w;
    }
#pragma unroll
    for (int o = 16; o; o >>= 1) s += __shfl_xor_sync(0xffffffffu, s, o);
    if (lane == 0) out[v] = s;
}

// ---------------- launcher ----------------
extern "C" void kernel_launch(void* const* d_in, const int* in_sizes, int n_in,
                              void* d_out, int out_size)
{
    const float* hidden = (const float*)d_in[0];
    const float* qkv_w  = (const float*)d_in[1];
    const float* qknw   = (const float*)d_in[2];
    const float* o_w    = (const float*)d_in[3];
    const float* gu_w   = (const float*)d_in[4];
    const float* dn_w   = (const float*)d_in[5];
    const float* lm_w   = (const float*)d_in[6];
    const float* cosb   = (const float*)d_in[7];
    const float* sinb   = (const float*)d_in[8];
    const float* maskp  = (const float*)d_in[9];
    float* outp = (float*)d_out;

    const int SMEMB = 2 * 65536 + 1024;    // 132096
    cudaFuncSetAttribute(hmma_gemm, cudaFuncAttributeMaxDynamicSharedMemorySize, SMEMB);

    float *px, *pqkv, *psc, *pgu, *plast;
    bf16 *phnh, *phnl, *pwh, *pwl, *pqh, *pql, *pkh, *pkl, *pvth, *pvtl,
         *pph, *ppl, *ppaoh, *ppaol, *pacth, *pactl;
    cudaGetSymbolAddress((void**)&px,    g_x);
    cudaGetSymbolAddress((void**)&phnh,  g_hnh);
    cudaGetSymbolAddress((void**)&phnl,  g_hnl);
    cudaGetSymbolAddress((void**)&pwh,   g_wh);
    cudaGetSymbolAddress((void**)&pwl,   g_wl);
    cudaGetSymbolAddress((void**)&pqkv,  g_qkv);
    cudaGetSymbolAddress((void**)&pqh,   g_qh);
    cudaGetSymbolAddress((void**)&pql,   g_ql);
    cudaGetSymbolAddress((void**)&pkh,   g_kh);
    cudaGetSymbolAddress((void**)&pkl,   g_kl);
    cudaGetSymbolAddress((void**)&pvth,  g_vth);
    cudaGetSymbolAddress((void**)&pvtl,  g_vtl);
    cudaGetSymbolAddress((void**)&psc,   g_sc);
    cudaGetSymbolAddress((void**)&pph,   g_ph);
    cudaGetSymbolAddress((void**)&ppl,   g_pl);
    cudaGetSymbolAddress((void**)&ppaoh, g_paoh);
    cudaGetSymbolAddress((void**)&ppaol, g_paol);
    cudaGetSymbolAddress((void**)&pgu,   g_gu);
    cudaGetSymbolAddress((void**)&pacth, g_acth);
    cudaGetSymbolAddress((void**)&pactl, g_actl);
    cudaGetSymbolAddress((void**)&plast, g_last);

    const float* xin = hidden;

    for (int l = 0; l < NLAY; l++) {
        l2norm_rows_split<<<SEQ, 256>>>(xin, phnh, phnl, HDIM);

        // QKV projection
        {
            long long n4 = (long long)QKVO * HDIM / 4;
            split4<<<(unsigned)((n4 + 255) / 256), 256>>>(
                (const float4*)(qkv_w + (long long)l * QKVO * HDIM), (uint2*)pwh, (uint2*)pwl, n4);
        }
        hmma_gemm<<<dim3(QKVO / 128, SEQ / 128, 1), 256, SMEMB>>>(
            phnh, phnl, HDIM, pwh, pwl, HDIM, pqkv, QKVO, HDIM,
            nullptr, 0, nullptr, nullptr, 0, 0, 0, 0);

        qk_rope_split<<<dim3(SEQ, QKH), 128>>>(pqkv, qknw + (long long)l * QKH * HD,
                                               cosb, sinb, pqh, pql, pkh, pkl);
        v_transpose_split<<<dim3(SEQ / 32, HD / 32, KVH), dim3(32, 32)>>>(pqkv, pvth, pvtl);

        // scores = Q K^T per head
        hmma_gemm<<<dim3(SEQ / 128, SEQ / 128, NH), 256, SMEMB>>>(
            pqh, pql, HD, pkh, pkl, HD, psc, SEQ, HD,
            nullptr, 0, nullptr, nullptr,
            (long long)SEQ * HD, (long long)SEQ * HD, (long long)SEQ * SEQ, 1);

        softmax_causal_split<<<dim3(SEQ, NH), 256>>>(psc, maskp, pph, ppl);

        // out = P V (bf16 split output slab per head)
        hmma_gemm<<<dim3(1, SEQ / 128, NH), 256, SMEMB>>>(
            pph, ppl, SEQ, pvth, pvtl, SEQ, nullptr, HDIM, SEQ,
            nullptr, 0, ppaoh, ppaol,
            (long long)SEQ * SEQ, (long long)HD * SEQ, (long long)HD, 1);

        // O projection + residual
        {
            long long n4 = (long long)HDIM * HDIM / 4;
            split4<<<(unsigned)((n4 + 255) / 256), 256>>>(
                (const float4*)(o_w + (long long)l * HDIM * HDIM), (uint2*)pwh, (uint2*)pwl, n4);
        }
        hmma_gemm<<<dim3(HDIM / 128, SEQ / 128, 1), 256, SMEMB>>>(
            ppaoh, ppaol, HDIM, pwh, pwl, HDIM, px, HDIM, HDIM,
            xin, HDIM, nullptr, nullptr, 0, 0, 0, 0);

        // MLP
        l2norm_rows_split<<<SEQ, 256>>>(px, phnh, phnl, HDIM);
        {
            long long n4 = (long long)2 * DFF * HDIM / 4;
            split4<<<(unsigned)((n4 + 255) / 256), 256>>>(
                (const float4*)(gu_w + (long long)l * 2 * DFF * HDIM), (uint2*)pwh, (uint2*)pwl, n4);
        }
        hmma_gemm<<<dim3(2 * DFF / 128, SEQ / 128, 1), 256, SMEMB>>>(
            phnh, phnl, HDIM, pwh, pwl, HDIM, pgu, 2 * DFF, HDIM,
            nullptr, 0, nullptr, nullptr, 0, 0, 0, 0);
        silu_mul_split<<<(SEQ * DFF) / 256, 256>>>(pgu, pacth, pactl);
        {
            long long n4 = (long long)HDIM * DFF / 4;
            split4<<<(unsigned)((n4 + 255) / 256), 256>>>(
                (const float4*)(dn_w + (long long)l * HDIM * DFF), (uint2*)pwh, (uint2*)pwl, n4);
        }
        hmma_gemm<<<dim3(HDIM / 128, SEQ / 128, 1), 256, SMEMB>>>(
            pacth, pactl, DFF, pwh, pwl, DFF, px, HDIM, DFF,
            px, HDIM, nullptr, nullptr, 0, 0, 0, 0);

        xin = px;
    }

    l2norm_rows<<<1, 256>>>(px + (long long)(SEQ - 1) * HDIM, plast, HDIM);
    lm_head<<<VOC / 8, 256>>>(plast, lm_w, outp);
}

// round 5
// speedup vs baseline: 2.9850x; 1.0249x over previous
#include <cuda_runtime.h>
#include <cuda_bf16.h>
#include <stdint.h>
#include <math.h>

#define SEQ   1024
#define HDIM  2048
#define NH    16
#define KVH   8
#define HD    128
#define QKH   24
#define QKVO  4096
#define DFF   6144
#define VOC   32000
#define NLAY  2

typedef __nv_bfloat16 bf16;

// ---------------- device scratch (no allocs allowed) ----------------
__device__ __align__(16) float g_x   [SEQ*HDIM];
__device__ __align__(16) bf16  g_hnh [SEQ*HDIM];
__device__ __align__(16) bf16  g_hnl [SEQ*HDIM];
__device__ __align__(16) bf16  g_wh  [2*DFF*HDIM];
__device__ __align__(16) bf16  g_wl  [2*DFF*HDIM];
__device__ __align__(16) float g_qkv [SEQ*QKVO];
__device__ __align__(16) bf16  g_qh  [NH*SEQ*HD];
__device__ __align__(16) bf16  g_ql  [NH*SEQ*HD];
__device__ __align__(16) bf16  g_kh  [KVH*SEQ*HD];
__device__ __align__(16) bf16  g_kl  [KVH*SEQ*HD];
__device__ __align__(16) bf16  g_vth [KVH*HD*SEQ];
__device__ __align__(16) bf16  g_vtl [KVH*HD*SEQ];
__device__ __align__(16) float g_sc  [NH*SEQ*SEQ];
__device__ __align__(16) bf16  g_ph  [NH*SEQ*SEQ];
__device__ __align__(16) bf16  g_pl  [NH*SEQ*SEQ];
__device__ __align__(16) bf16  g_paoh[SEQ*HDIM];
__device__ __align__(16) bf16  g_paol[SEQ*HDIM];
__device__ __align__(16) float g_gu  [SEQ*2*DFF];
__device__ __align__(16) bf16  g_acth[SEQ*DFF];
__device__ __align__(16) bf16  g_actl[SEQ*DFF];
__device__ __align__(16) float g_last[HDIM];

// ---------------- helpers ----------------
__device__ __forceinline__ uint32_t smem_u32(const void* p) {
    uint32_t a;
    asm("{ .reg .u64 t; cvta.to.shared.u64 t, %1; cvt.u32.u64 %0, t; }" : "=r"(a) : "l"(p));
    return a;
}
__device__ __forceinline__ uint32_t pack2(bf16 a, bf16 b) {
    return (uint32_t)__bfloat16_as_ushort(a) | ((uint32_t)__bfloat16_as_ushort(b) << 16);
}
__device__ __forceinline__ void split2(float x, bf16& h, bf16& l) {
    h = __float2bfloat16_rn(x);
    l = __float2bfloat16_rn(x - __bfloat162float(h));
}

#define CPA16(d, s) asm volatile("cp.async.cg.shared.global [%0], [%1], 16;" :: "r"(d), "l"(s))
#define CPA_COMMIT() asm volatile("cp.async.commit_group;" ::: "memory")
#define CPA_WAIT(n)  asm volatile("cp.async.wait_group %0;" :: "n"(n) : "memory")

#define LDSM4(r, a) \
    asm volatile("ldmatrix.sync.aligned.m8n8.x4.shared.b16 {%0,%1,%2,%3}, [%4];" \
        : "=r"((r)[0]), "=r"((r)[1]), "=r"((r)[2]), "=r"((r)[3]) : "r"(a))

#define MMA16816(c, a, b) \
    asm volatile("mma.sync.aligned.m16n8k16.row.col.f32.bf16.bf16.f32 " \
        "{%0,%1,%2,%3}, {%4,%5,%6,%7}, {%8,%9}, {%0,%1,%2,%3};" \
        : "+f"((c)[0]), "+f"((c)[1]), "+f"((c)[2]), "+f"((c)[3]) \
        : "r"((a)[0]), "r"((a)[1]), "r"((a)[2]), "r"((a)[3]), "r"((b)[0]), "r"((b)[1]))

// ============================================================================
// HMMA bf16 3-term-split GEMM (NT): C[z](128x128 tile) = A(MxK) * B(NxK)^T
// blockIdx.x = M-tile (fastest -> L2 reuse of B across M), blockIdx.y = N-tile.
// causal bit0: skip tiles with n0 > m0 (scores). bit1: K-limit to m0+128 (PV).
// 3-stage cp.async pipeline; stage = [Ah 16K][Al 16K][Bh 16K][Bl 16K].
// ============================================================================
__global__ __launch_bounds__(256)
void hmma_gemm(const bf16* __restrict__ Ah, const bf16* __restrict__ Al, int lda,
               const bf16* __restrict__ Bh, const bf16* __restrict__ Bl, int ldb,
               float* __restrict__ C, int ldc, int K,
               const float* __restrict__ resid, int ldr,
               bf16* __restrict__ Chi, bf16* __restrict__ Clo,
               long long bsA, long long bsB, long long bsC, int bShiftB, int causal)
{
    constexpr int STAGE = 65536;
    extern __shared__ char dynraw[];
    char* sm = (char*)(((uintptr_t)dynraw + 1023) & ~(uintptr_t)1023);
    const uint32_t smb = smem_u32(sm);

    const int m0 = blockIdx.x * 128;
    const int n0 = blockIdx.y * 128;
    if ((causal & 1) && n0 > m0) return;

    const int tid  = threadIdx.x;
    const int lane = tid & 31;
    const int wid  = tid >> 5;
    const int wm   = (wid >> 2) * 64;
    const int wn   = (wid & 3) * 32;

    const long long z = blockIdx.z;
    Ah += z * bsA;  Al += z * bsA;
    Bh += (z >> bShiftB) * bsB;  Bl += (z >> bShiftB) * bsB;
    if (C)   C   += z * bsC;
    if (Chi) { Chi += z * bsC; Clo += z * bsC; }

    const int Keff = (causal & 2) ? min(K, m0 + 128) : K;
    const int nch  = Keff >> 6;

    const int a_row_l  = lane & 15;
    const int a_colq_l = lane >> 4;
    const int b_row_l  = (lane & 7) + ((lane & 16) >> 1);
    const int b_colq_l = (lane >> 3) & 1;

    float acc[4][4][4];
#pragma unroll
    for (int i = 0; i < 4; i++)
#pragma unroll
        for (int j = 0; j < 4; j++)
#pragma unroll
            for (int q = 0; q < 4; q++) acc[i][j][q] = 0.f;

    auto load_chunk = [&](int c) {
        const int k0 = c << 6;
        const uint32_t st = smb + (c % 3) * STAGE;
#pragma unroll
        for (int it = 0; it < 16; it++) {
            const int g   = it * 256 + tid;
            const int arr = it >> 2;
            const int r   = (g >> 3) & 127;
            const int q   = g & 7;
            const bf16* src;
            if      (arr == 0) src = Ah + (size_t)(m0 + r) * lda + k0 + q * 8;
            else if (arr == 1) src = Al + (size_t)(m0 + r) * lda + k0 + q * 8;
            else if (arr == 2) src = Bh + (size_t)(n0 + r) * ldb + k0 + q * 8;
            else               src = Bl + (size_t)(n0 + r) * ldb + k0 + q * 8;
            const uint32_t dst = st + arr * 16384 + r * 128 + ((q ^ (r & 7)) << 4);
            CPA16(dst, src);
        }
        CPA_COMMIT();
    };

    load_chunk(0);
    if (nch > 1) load_chunk(1);

    for (int c = 0; c < nch; c++) {
        if (c + 2 < nch)      { load_chunk(c + 2); CPA_WAIT(2); }
        else if (c + 1 < nch) { CPA_WAIT(1); }
        else                  { CPA_WAIT(0); }
        __syncthreads();

        const uint32_t st = smb + (c % 3) * STAGE;
        const uint32_t sAh = st, sAl = st + 16384, sBh = st + 32768, sBl = st + 49152;

#pragma unroll
        for (int kk = 0; kk < 4; kk++) {
            uint32_t ahf[4][4], alf[4][4], bhf[4][2], blf[4][2];
            const int acq = kk * 2 + a_colq_l;
#pragma unroll
            for (int mi = 0; mi < 4; mi++) {
                const int r = wm + mi * 16 + a_row_l;
                const uint32_t off = r * 128 + ((acq ^ (r & 7)) << 4);
                LDSM4(ahf[mi], sAh + off);
                LDSM4(alf[mi], sAl + off);
            }
            const int bcq = kk * 2 + b_colq_l;
#pragma unroll
            for (int nj = 0; nj < 2; nj++) {
                const int r = wn + nj * 16 + b_row_l;
                const uint32_t off = r * 128 + ((bcq ^ (r & 7)) << 4);
                uint32_t t4[4];
                LDSM4(t4, sBh + off);
                bhf[nj*2][0] = t4[0]; bhf[nj*2][1] = t4[1];
                bhf[nj*2+1][0] = t4[2]; bhf[nj*2+1][1] = t4[3];
                LDSM4(t4, sBl + off);
                blf[nj*2][0] = t4[0]; blf[nj*2][1] = t4[1];
                blf[nj*2+1][0] = t4[2]; blf[nj*2+1][1] = t4[3];
            }
#pragma unroll
            for (int mi = 0; mi < 4; mi++)
#pragma unroll
                for (int ni = 0; ni < 4; ni++) {
                    MMA16816(acc[mi][ni], ahf[mi], bhf[ni]);
                    MMA16816(acc[mi][ni], ahf[mi], blf[ni]);
                    MMA16816(acc[mi][ni], alf[mi], bhf[ni]);
                }
        }
        __syncthreads();
    }

    // ---- epilogue ----
    const int g = lane >> 2, t = lane & 3;
#pragma unroll
    for (int mi = 0; mi < 4; mi++)
#pragma unroll
        for (int ni = 0; ni < 4; ni++)
#pragma unroll
            for (int half = 0; half < 2; half++) {
                const int row = m0 + wm + mi * 16 + g + half * 8;
                const int col = n0 + wn + ni * 8 + 2 * t;
                float v0 = acc[mi][ni][half * 2 + 0];
                float v1 = acc[mi][ni][half * 2 + 1];
                if (resid) {
                    const float* rp = resid + (size_t)row * ldr + col;
                    v0 += rp[0]; v1 += rp[1];
                }
                if (C) *(float2*)(C + (size_t)row * ldc + col) = make_float2(v0, v1);
                if (Chi) {
                    bf16 h0, l0, h1, l1;
                    split2(v0, h0, l0); split2(v1, h1, l1);
                    *(uint32_t*)(Chi + (size_t)row * ldc + col) = pack2(h0, h1);
                    *(uint32_t*)(Clo + (size_t)row * ldc + col) = pack2(l0, l1);
                }
            }
}

// ---------------- fp32 -> (hi,lo) bf16 split, 4 elems/thread ----------------
__global__ void split4(const float4* __restrict__ in, uint2* __restrict__ hi,
                       uint2* __restrict__ lo, long long n4)
{
    long long i = (long long)blockIdx.x * blockDim.x + threadIdx.x;
    if (i >= n4) return;
    float4 v = in[i];
    bf16 h0, l0, h1, l1, h2, l2, h3, l3;
    split2(v.x, h0, l0); split2(v.y, h1, l1); split2(v.z, h2, l2); split2(v.w, h3, l3);
    hi[i] = make_uint2(pack2(h0, h1), pack2(h2, h3));
    lo[i] = make_uint2(pack2(l0, l1), pack2(l2, l3));
}

// ---------------- row l2norm -> split bf16 ----------------
__global__ void l2norm_rows_split(const float* __restrict__ in, bf16* __restrict__ hi,
                                  bf16* __restrict__ lo, int cols)
{
    const int row = blockIdx.x;
    const float* x = in + (long long)row * cols;
    float s = 0.f;
    for (int c = threadIdx.x; c < cols; c += blockDim.x) { float v = x[c]; s += v * v; }
    __shared__ float red[32];
#pragma unroll
    for (int o = 16; o; o >>= 1) s += __shfl_xor_sync(0xffffffffu, s, o);
    if ((threadIdx.x & 31) == 0) red[threadIdx.x >> 5] = s;
    __syncthreads();
    const int nw = blockDim.x >> 5;
    if (threadIdx.x < 32) {
        float t = (threadIdx.x < nw) ? red[threadIdx.x] : 0.f;
#pragma unroll
        for (int o = 16; o; o >>= 1) t += __shfl_xor_sync(0xffffffffu, t, o);
        if (threadIdx.x == 0) red[0] = rsqrtf(t);
    }
    __syncthreads();
    const float r = red[0];
    for (int c = threadIdx.x; c < cols; c += blockDim.x) {
        bf16 h, l;
        split2(x[c] * r, h, l);
        hi[(long long)row * cols + c] = h;
        lo[(long long)row * cols + c] = l;
    }
}

__global__ void l2norm_rows(const float* __restrict__ in, float* __restrict__ out, int cols)
{
    const int row = blockIdx.x;
    const float* x = in + (long long)row * cols;
    float* y = out + (long long)row * cols;
    float s = 0.f;
    for (int c = threadIdx.x; c < cols; c += blockDim.x) { float v = x[c]; s += v * v; }
    __shared__ float red[32];
#pragma unroll
    for (int o = 16; o; o >>= 1) s += __shfl_xor_sync(0xffffffffu, s, o);
    if ((threadIdx.x & 31) == 0) red[threadIdx.x >> 5] = s;
    __syncthreads();
    const int nw = blockDim.x >> 5;
    if (threadIdx.x < 32) {
        float t = (threadIdx.x < nw) ? red[threadIdx.x] : 0.f;
#pragma unroll
        for (int o = 16; o; o >>= 1) t += __shfl_xor_sync(0xffffffffu, t, o);
        if (threadIdx.x == 0) red[0] = rsqrtf(t);
    }
    __syncthreads();
    const float r = red[0];
    for (int c = threadIdx.x; c < cols; c += blockDim.x) y[c] = x[c] * r;
}

// ---------------- per-head norm + RoPE -> split Q/K ----------------
__global__ void qk_rope_split(const float* __restrict__ qkv, const float* __restrict__ qknw,
                              const float* __restrict__ cosb, const float* __restrict__ sinb,
                              bf16* __restrict__ Qh, bf16* __restrict__ Ql,
                              bf16* __restrict__ Kh, bf16* __restrict__ Kl)
{
    const int s = blockIdx.x;
    const int h = blockIdx.y;
    const int d = threadIdx.x;
    __shared__ float sv[128];
    __shared__ float red[4];

    float v = qkv[(long long)s * QKVO + h * HD + d];
    float ss = v * v;
#pragma unroll
    for (int o = 16; o; o >>= 1) ss += __shfl_xor_sync(0xffffffffu, ss, o);
    if ((d & 31) == 0) red[d >> 5] = ss;
    __syncthreads();
    const float tot = red[0] + red[1] + red[2] + red[3];
    const float nv = v * rsqrtf(tot) * qknw[h * HD + d];
    sv[d] = nv;
    __syncthreads();
    const float rot = (d < 64) ? sv[d + 64] : sv[d - 64];
    const float ov = nv * cosb[s * HD + d] + rot * sinb[s * HD + d];
    bf16 hh, ll;
    split2(ov, hh, ll);
    if (h < NH) {
        size_t o = ((size_t)h * SEQ + s) * HD + d;
        Qh[o] = hh; Ql[o] = ll;
    } else {
        size_t o = ((size_t)(h - NH) * SEQ + s) * HD + d;
        Kh[o] = hh; Kl[o] = ll;
    }
}

// ---------------- V transpose -> split ----------------
__global__ void v_transpose_split(const float* __restrict__ qkv,
                                  bf16* __restrict__ Vth, bf16* __restrict__ Vtl)
{
    __shared__ float t[32][33];
    const int h = blockIdx.z;
    const int s0 = blockIdx.x * 32;
    const int d0 = blockIdx.y * 32;
    t[threadIdx.y][threadIdx.x] =
        qkv[(long long)(s0 + threadIdx.y) * QKVO + QKH * HD + h * HD + d0 + threadIdx.x];
    __syncthreads();
    bf16 hh, ll;
    split2(t[threadIdx.x][threadIdx.y], hh, ll);
    size_t o = ((size_t)h * HD + d0 + threadIdx.y) * SEQ + s0 + threadIdx.x;
    Vth[o] = hh; Vtl[o] = ll;
}

// ---------------- causal softmax (K-limited) -> split probs ----------------
__global__ void softmax_causal_split(const float* __restrict__ scores, const float* __restrict__ maskp,
                                     bf16* __restrict__ Ph, bf16* __restrict__ Pl)
{
    const int q = blockIdx.x;
    const int h = blockIdx.y;
    const int kmax = ((q >> 7) + 1) << 7;      // only tiles PV will read
    const float* row = scores + ((long long)h * SEQ + q) * SEQ;
    const float mpen = -128.f * maskp[0];
    const int tid = threadIdx.x;

    float vals[4];
    float mx = -1e30f;
#pragma unroll
    for (int i = 0; i < 4; i++) {
        int k = tid + i * 256;
        if (k < kmax) {
            float v = row[k] + (k > q ? mpen : 0.f);
            vals[i] = v;
            mx = fmaxf(mx, v);
        } else vals[i] = -1e30f;
    }
    __shared__ float redm[8];
    __shared__ float reds[8];
#pragma unroll
    for (int o = 16; o; o >>= 1) mx = fmaxf(mx, __shfl_xor_sync(0xffffffffu, mx, o));
    if ((tid & 31) == 0) redm[tid >> 5] = mx;
    __syncthreads();
    if (tid < 32) {
        float m2 = (tid < 8) ? redm[tid] : -1e30f;
#pragma unroll
        for (int o = 16; o; o >>= 1) m2 = fmaxf(m2, __shfl_xor_sync(0xffffffffu, m2, o));
        if (tid == 0) redm[0] = m2;
    }
    __syncthreads();
    mx = redm[0];

    float s = 0.f;
#pragma unroll
    for (int i = 0; i < 4; i++) {
        int k = tid + i * 256;
        if (k < kmax) { vals[i] = expf(vals[i] - mx); s += vals[i]; }
    }
#pragma unroll
    for (int o = 16; o; o >>= 1) s += __shfl_xor_sync(0xffffffffu, s, o);
    if ((tid & 31) == 0) reds[tid >> 5] = s;
    __syncthreads();
    if (tid < 32) {
        float t2 = (tid < 8) ? reds[tid] : 0.f;
#pragma unroll
        for (int o = 16; o; o >>= 1) t2 += __shfl_xor_sync(0xffffffffu, t2, o);
        if (tid == 0) reds[0] = 1.f / t2;
    }
    __syncthreads();
    const float inv = reds[0];
    const size_t base = ((size_t)h * SEQ + q) * SEQ;
#pragma unroll
    for (int i = 0; i < 4; i++) {
        int k = tid + i * 256;
        if (k < kmax) {
            bf16 hh, ll;
            split2(vals[i] * inv, hh, ll);
            Ph[base + k] = hh;
            Pl[base + k] = ll;
        }
    }
}

// ---------------- SwiGLU -> split ----------------
__global__ void silu_mul_split(const float* __restrict__ gu, bf16* __restrict__ Ah, bf16* __restrict__ Al)
{
    const long long i = (long long)blockIdx.x * blockDim.x + threadIdx.x;
    const int s = (int)(i / DFF);
    const int f = (int)(i % DFF);
    const float g = gu[(long long)s * (2 * DFF) + f];
    const float u = gu[(long long)s * (2 * DFF) + DFF + f];
    bf16 hh, ll;
    split2((g / (1.f + expf(-g))) * u, hh, ll);
    Ah[i] = hh; Al[i] = ll;
}

// ---------------- lm_head GEMV (fp32) ----------------
__global__ void lm_head(const float* __restrict__ last, const float* __restrict__ W,
                        float* __restrict__ out)
{
    const int warp = threadIdx.x >> 5;
    const int lane = threadIdx.x & 31;
    const int v = blockIdx.x * 8 + warp;
    const float* w = W + (long long)v * HDIM;
    float s = 0.f;
#pragma unroll
    for (int j = lane * 4; j < HDIM; j += 128) {
        float4 wv = *(const float4*)(w + j);
        float4 lv = *(const float4*)(last + j);
        s += wv.x * lv.x + wv.y * lv.y + wv.z * lv.z + wv.w * lv.w;
    }
#pragma unroll
    for (int o = 16; o; o >>= 1) s += __shfl_xor_sync(0xffffffffu, s, o);
    if (lane == 0) out[v] = s;
}

// ---------------- launcher ----------------
extern "C" void kernel_launch(void* const* d_in, const int* in_sizes, int n_in,
                              void* d_out, int out_size)
{
    const float* hidden = (const float*)d_in[0];
    const float* qkv_w  = (const float*)d_in[1];
    const float* qknw   = (const float*)d_in[2];
    const float* o_w    = (const float*)d_in[3];
    const float* gu_w   = (const float*)d_in[4];
    const float* dn_w   = (const float*)d_in[5];
    const float* lm_w   = (const float*)d_in[6];
    const float* cosb   = (const float*)d_in[7];
    const float* sinb   = (const float*)d_in[8];
    const float* maskp  = (const float*)d_in[9];
    float* outp = (float*)d_out;

    const int SMEMB = 3 * 65536 + 1024;    // 197632, 1 CTA/SM
    cudaFuncSetAttribute(hmma_gemm, cudaFuncAttributeMaxDynamicSharedMemorySize, SMEMB);

    float *px, *pqkv, *psc, *pgu, *plast;
    bf16 *phnh, *phnl, *pwh, *pwl, *pqh, *pql, *pkh, *pkl, *pvth, *pvtl,
         *pph, *ppl, *ppaoh, *ppaol, *pacth, *pactl;
    cudaGetSymbolAddress((void**)&px,    g_x);
    cudaGetSymbolAddress((void**)&phnh,  g_hnh);
    cudaGetSymbolAddress((void**)&phnl,  g_hnl);
    cudaGetSymbolAddress((void**)&pwh,   g_wh);
    cudaGetSymbolAddress((void**)&pwl,   g_wl);
    cudaGetSymbolAddress((void**)&pqkv,  g_qkv);
    cudaGetSymbolAddress((void**)&pqh,   g_qh);
    cudaGetSymbolAddress((void**)&pql,   g_ql);
    cudaGetSymbolAddress((void**)&pkh,   g_kh);
    cudaGetSymbolAddress((void**)&pkl,   g_kl);
    cudaGetSymbolAddress((void**)&pvth,  g_vth);
    cudaGetSymbolAddress((void**)&pvtl,  g_vtl);
    cudaGetSymbolAddress((void**)&psc,   g_sc);
    cudaGetSymbolAddress((void**)&pph,   g_ph);
    cudaGetSymbolAddress((void**)&ppl,   g_pl);
    cudaGetSymbolAddress((void**)&ppaoh, g_paoh);
    cudaGetSymbolAddress((void**)&ppaol, g_paol);
    cudaGetSymbolAddress((void**)&pgu,   g_gu);
    cudaGetSymbolAddress((void**)&pacth, g_acth);
    cudaGetSymbolAddress((void**)&pactl, g_actl);
    cudaGetSymbolAddress((void**)&plast, g_last);

    const float* xin = hidden;

    for (int l = 0; l < NLAY; l++) {
        l2norm_rows_split<<<SEQ, 256>>>(xin, phnh, phnl, HDIM);

        // QKV projection
        {
            long long n4 = (long long)QKVO * HDIM / 4;
            split4<<<(unsigned)((n4 + 255) / 256), 256>>>(
                (const float4*)(qkv_w + (long long)l * QKVO * HDIM), (uint2*)pwh, (uint2*)pwl, n4);
        }
        hmma_gemm<<<dim3(SEQ / 128, QKVO / 128, 1), 256, SMEMB>>>(
            phnh, phnl, HDIM, pwh, pwl, HDIM, pqkv, QKVO, HDIM,
            nullptr, 0, nullptr, nullptr, 0, 0, 0, 0, 0);

        qk_rope_split<<<dim3(SEQ, QKH), 128>>>(pqkv, qknw + (long long)l * QKH * HD,
                                               cosb, sinb, pqh, pql, pkh, pkl);
        v_transpose_split<<<dim3(SEQ / 32, HD / 32, KVH), dim3(32, 32)>>>(pqkv, pvth, pvtl);

        // scores = Q K^T per head (skip upper-triangle tiles)
        hmma_gemm<<<dim3(SEQ / 128, SEQ / 128, NH), 256, SMEMB>>>(
            pqh, pql, HD, pkh, pkl, HD, psc, SEQ, HD,
            nullptr, 0, nullptr, nullptr,
            (long long)SEQ * HD, (long long)SEQ * HD, (long long)SEQ * SEQ, 1, 1);

        softmax_causal_split<<<dim3(SEQ, NH), 256>>>(psc, maskp, pph, ppl);

        // out = P V (K-limited per row block)
        hmma_gemm<<<dim3(SEQ / 128, 1, NH), 256, SMEMB>>>(
            pph, ppl, SEQ, pvth, pvtl, SEQ, nullptr, HDIM, SEQ,
            nullptr, 0, ppaoh, ppaol,
            (long long)SEQ * SEQ, (long long)HD * SEQ, (long long)HD, 1, 2);

        // O projection + residual
        {
            long long n4 = (long long)HDIM * HDIM / 4;
            split4<<<(unsigned)((n4 + 255) / 256), 256>>>(
                (const float4*)(o_w + (long long)l * HDIM * HDIM), (uint2*)pwh, (uint2*)pwl, n4);
        }
        hmma_gemm<<<dim3(SEQ / 128, HDIM / 128, 1), 256, SMEMB>>>(
            ppaoh, ppaol, HDIM, pwh, pwl, HDIM, px, HDIM, HDIM,
            xin, HDIM, nullptr, nullptr, 0, 0, 0, 0, 0);

        // MLP
        l2norm_rows_split<<<SEQ, 256>>>(px, phnh, phnl, HDIM);
        {
            long long n4 = (long long)2 * DFF * HDIM / 4;
            split4<<<(unsigned)((n4 + 255) / 256), 256>>>(
                (const float4*)(gu_w + (long long)l * 2 * DFF * HDIM), (uint2*)pwh, (uint2*)pwl, n4);
        }
        hmma_gemm<<<dim3(SEQ / 128, 2 * DFF / 128, 1), 256, SMEMB>>>(
            phnh, phnl, HDIM, pwh, pwl, HDIM, pgu, 2 * DFF, HDIM,
            nullptr, 0, nullptr, nullptr, 0, 0, 0, 0, 0);
        silu_mul_split<<<(SEQ * DFF) / 256, 256>>>(pgu, pacth, pactl);
        {
            long long n4 = (long long)HDIM * DFF / 4;
            split4<<<(unsigned)((n4 + 255) / 256), 256>>>(
                (const float4*)(dn_w + (long long)l * HDIM * DFF), (uint2*)pwh, (uint2*)pwl, n4);
        }
        hmma_gemm<<<dim3(SEQ / 128, HDIM / 128, 1), 256, SMEMB>>>(
            pacth, pactl, DFF, pwh, pwl, DFF, px, HDIM, DFF,
            px, HDIM, nullptr, nullptr, 0, 0, 0, 0, 0);

        xin = px;
    }

    l2norm_rows<<<1, 256>>>(px + (long long)(SEQ - 1) * HDIM, plast, HDIM);
    lm_head<<<VOC / 8, 256>>>(plast, lm_w, outp);
}

// round 6
// speedup vs baseline: 5.9830x; 2.0043x over previous
#include <cuda_runtime.h>
#include <cuda_bf16.h>
#include <cuda_fp16.h>
#include <stdint.h>
#include <math.h>

#define SEQ   1024
#define HDIM  2048
#define NH    16
#define KVH   8
#define HD    128
#define QKH   24
#define QKVO  4096
#define DFF   6144
#define VOC   32000
#define NLAY  2

typedef __nv_bfloat16 bf16;

// ---------------- device scratch (no allocs allowed) ----------------
__device__ __align__(16) float g_x   [SEQ*HDIM];
__device__ __align__(16) half  g_hnf [SEQ*HDIM];        // fp16 l2norm output
__device__ __align__(16) half  g_whf [2*DFF*HDIM];      // fp16 weights (largest)
__device__ __align__(16) float g_qkv [SEQ*QKVO];
__device__ __align__(16) bf16  g_qh  [NH*SEQ*HD];
__device__ __align__(16) bf16  g_ql  [NH*SEQ*HD];
__device__ __align__(16) bf16  g_kh  [KVH*SEQ*HD];
__device__ __align__(16) bf16  g_kl  [KVH*SEQ*HD];
__device__ __align__(16) bf16  g_vth [KVH*HD*SEQ];
__device__ __align__(16) bf16  g_vtl [KVH*HD*SEQ];
__device__ __align__(16) float g_sc  [NH*SEQ*SEQ];
__device__ __align__(16) bf16  g_ph  [NH*SEQ*SEQ];
__device__ __align__(16) bf16  g_pl  [NH*SEQ*SEQ];
__device__ __align__(16) half  g_paof[SEQ*HDIM];        // fp16 attention output
__device__ __align__(16) float g_gu  [SEQ*2*DFF];
__device__ __align__(16) half  g_actf[SEQ*DFF];         // fp16 SwiGLU output
__device__ __align__(16) float g_last[HDIM];

// ---------------- helpers ----------------
__device__ __forceinline__ uint32_t smem_u32(const void* p) {
    uint32_t a;
    asm("{ .reg .u64 t; cvta.to.shared.u64 t, %1; cvt.u32.u64 %0, t; }" : "=r"(a) : "l"(p));
    return a;
}
__device__ __forceinline__ uint32_t pack2(bf16 a, bf16 b) {
    return (uint32_t)__bfloat16_as_ushort(a) | ((uint32_t)__bfloat16_as_ushort(b) << 16);
}
__device__ __forceinline__ uint32_t pack2h(half a, half b) {
    return (uint32_t)__half_as_ushort(a) | ((uint32_t)__half_as_ushort(b) << 16);
}
__device__ __forceinline__ void split2(float x, bf16& h, bf16& l) {
    h = __float2bfloat16_rn(x);
    l = __float2bfloat16_rn(x - __bfloat162float(h));
}

#define CPA16(d, s) asm volatile("cp.async.cg.shared.global [%0], [%1], 16;" :: "r"(d), "l"(s))
#define CPA_COMMIT() asm volatile("cp.async.commit_group;" ::: "memory")
#define CPA_WAIT(n)  asm volatile("cp.async.wait_group %0;" :: "n"(n) : "memory")

#define LDSM4(r, a) \
    asm volatile("ldmatrix.sync.aligned.m8n8.x4.shared.b16 {%0,%1,%2,%3}, [%4];" \
        : "=r"((r)[0]), "=r"((r)[1]), "=r"((r)[2]), "=r"((r)[3]) : "r"(a))

#define MMA_BF16(c, a, b) \
    asm volatile("mma.sync.aligned.m16n8k16.row.col.f32.bf16.bf16.f32 " \
        "{%0,%1,%2,%3}, {%4,%5,%6,%7}, {%8,%9}, {%0,%1,%2,%3};" \
        : "+f"((c)[0]), "+f"((c)[1]), "+f"((c)[2]), "+f"((c)[3]) \
        : "r"((a)[0]), "r"((a)[1]), "r"((a)[2]), "r"((a)[3]), "r"((b)[0]), "r"((b)[1]))

#define MMA_F16(c, a, b) \
    asm volatile("mma.sync.aligned.m16n8k16.row.col.f32.f16.f16.f32 " \
        "{%0,%1,%2,%3}, {%4,%5,%6,%7}, {%8,%9}, {%0,%1,%2,%3};" \
        : "+f"((c)[0]), "+f"((c)[1]), "+f"((c)[2]), "+f"((c)[3]) \
        : "r"((a)[0]), "r"((a)[1]), "r"((a)[2]), "r"((a)[3]), "r"((b)[0]), "r"((b)[1]))

// ============================================================================
// fp16 single-term GEMM (NT): C = A(MxK) * B(NxK)^T (+resid), fp32 out.
// 128x128 tile, 3-stage cp.async, stage=[A 16K][B 16K]=32KB -> 2 CTAs/SM.
// ============================================================================
__global__ __launch_bounds__(256, 2)
void hgemm1(const half* __restrict__ A, int lda,
            const half* __restrict__ B, int ldb,
            float* __restrict__ C, int ldc, int K,
            const float* __restrict__ resid, int ldr)
{
    constexpr int STG = 32768;
    extern __shared__ char dynraw[];
    char* sm = (char*)(((uintptr_t)dynraw + 1023) & ~(uintptr_t)1023);
    const uint32_t smb = smem_u32(sm);

    const int m0 = blockIdx.x * 128;
    const int n0 = blockIdx.y * 128;
    const int tid  = threadIdx.x;
    const int lane = tid & 31;
    const int wid  = tid >> 5;
    const int wm   = (wid >> 2) * 64;
    const int wn   = (wid & 3) * 32;

    const int a_row_l  = lane & 15;
    const int a_colq_l = lane >> 4;
    const int b_row_l  = (lane & 7) + ((lane & 16) >> 1);
    const int b_colq_l = (lane >> 3) & 1;

    float acc[4][4][4];
#pragma unroll
    for (int i = 0; i < 4; i++)
#pragma unroll
        for (int j = 0; j < 4; j++)
#pragma unroll
            for (int q = 0; q < 4; q++) acc[i][j][q] = 0.f;

    auto load_chunk = [&](int c) {
        const int k0 = c << 6;
        const uint32_t st = smb + (c % 3) * STG;
#pragma unroll
        for (int it = 0; it < 8; it++) {
            const int g   = it * 256 + tid;
            const int arr = it >> 2;
            const int r   = (g >> 3) & 127;
            const int q   = g & 7;
            const half* src = arr ? (B + (size_t)(n0 + r) * ldb + k0 + q * 8)
                                  : (A + (size_t)(m0 + r) * lda + k0 + q * 8);
            const uint32_t dst = st + arr * 16384 + r * 128 + ((q ^ (r & 7)) << 4);
            CPA16(dst, src);
        }
        CPA_COMMIT();
    };

    const int nch = K >> 6;
    load_chunk(0);
    if (nch > 1) load_chunk(1);

    for (int c = 0; c < nch; c++) {
        if (c + 2 < nch)      { load_chunk(c + 2); CPA_WAIT(2); }
        else if (c + 1 < nch) { CPA_WAIT(1); }
        else                  { CPA_WAIT(0); }
        __syncthreads();

        const uint32_t st = smb + (c % 3) * STG;
        const uint32_t sA = st, sB = st + 16384;

#pragma unroll
        for (int kk = 0; kk < 4; kk++) {
            uint32_t af[4][4], bfr[4][2];
            const int acq = kk * 2 + a_colq_l;
#pragma unroll
            for (int mi = 0; mi < 4; mi++) {
                const int r = wm + mi * 16 + a_row_l;
                LDSM4(af[mi], sA + r * 128 + ((acq ^ (r & 7)) << 4));
            }
            const int bcq = kk * 2 + b_colq_l;
#pragma unroll
            for (int nj = 0; nj < 2; nj++) {
                const int r = wn + nj * 16 + b_row_l;
                uint32_t t4[4];
                LDSM4(t4, sB + r * 128 + ((bcq ^ (r & 7)) << 4));
                bfr[nj*2][0] = t4[0]; bfr[nj*2][1] = t4[1];
                bfr[nj*2+1][0] = t4[2]; bfr[nj*2+1][1] = t4[3];
            }
#pragma unroll
            for (int mi = 0; mi < 4; mi++)
#pragma unroll
                for (int ni = 0; ni < 4; ni++)
                    MMA_F16(acc[mi][ni], af[mi], bfr[ni]);
        }
        __syncthreads();
    }

    const int g = lane >> 2, t = lane & 3;
#pragma unroll
    for (int mi = 0; mi < 4; mi++)
#pragma unroll
        for (int ni = 0; ni < 4; ni++)
#pragma unroll
            for (int half_ = 0; half_ < 2; half_++) {
                const int row = m0 + wm + mi * 16 + g + half_ * 8;
                const int col = n0 + wn + ni * 8 + 2 * t;
                float v0 = acc[mi][ni][half_ * 2 + 0];
                float v1 = acc[mi][ni][half_ * 2 + 1];
                if (resid) {
                    const float* rp = resid + (size_t)row * ldr + col;
                    v0 += rp[0]; v1 += rp[1];
                }
                *(float2*)(C + (size_t)row * ldc + col) = make_float2(v0, v1);
            }
}

// ============================================================================
// bf16 3-term-split GEMM (NT) for attention: near-fp32 accuracy.
// causal bit0: skip n0>m0 tiles (scores). bit1: K-limit to m0+128 (PV).
// Output: fp32 C, or fp16 Ch (PV -> o-proj input).
// ============================================================================
__global__ __launch_bounds__(256)
void hgemm3(const bf16* __restrict__ Ah, const bf16* __restrict__ Al, int lda,
            const bf16* __restrict__ Bh, const bf16* __restrict__ Bl, int ldb,
            float* __restrict__ C, half* __restrict__ Ch, int ldc, int K,
            long long bsA, long long bsB, long long bsC, int bShiftB, int causal)
{
    constexpr int STAGE = 65536;
    extern __shared__ char dynraw[];
    char* sm = (char*)(((uintptr_t)dynraw + 1023) & ~(uintptr_t)1023);
    const uint32_t smb = smem_u32(sm);

    const int m0 = blockIdx.x * 128;
    const int n0 = blockIdx.y * 128;
    if ((causal & 1) && n0 > m0) return;

    const int tid  = threadIdx.x;
    const int lane = tid & 31;
    const int wid  = tid >> 5;
    const int wm   = (wid >> 2) * 64;
    const int wn   = (wid & 3) * 32;

    const long long z = blockIdx.z;
    Ah += z * bsA;  Al += z * bsA;
    Bh += (z >> bShiftB) * bsB;  Bl += (z >> bShiftB) * bsB;
    if (C)  C  += z * bsC;
    if (Ch) Ch += z * bsC;

    const int Keff = (causal & 2) ? min(K, m0 + 128) : K;
    const int nch  = Keff >> 6;

    const int a_row_l  = lane & 15;
    const int a_colq_l = lane >> 4;
    const int b_row_l  = (lane & 7) + ((lane & 16) >> 1);
    const int b_colq_l = (lane >> 3) & 1;

    float acc[4][4][4];
#pragma unroll
    for (int i = 0; i < 4; i++)
#pragma unroll
        for (int j = 0; j < 4; j++)
#pragma unroll
            for (int q = 0; q < 4; q++) acc[i][j][q] = 0.f;

    auto load_chunk = [&](int c) {
        const int k0 = c << 6;
        const uint32_t st = smb + (c % 3) * STAGE;
#pragma unroll
        for (int it = 0; it < 16; it++) {
            const int g   = it * 256 + tid;
            const int arr = it >> 2;
            const int r   = (g >> 3) & 127;
            const int q   = g & 7;
            const bf16* src;
            if      (arr == 0) src = Ah + (size_t)(m0 + r) * lda + k0 + q * 8;
            else if (arr == 1) src = Al + (size_t)(m0 + r) * lda + k0 + q * 8;
            else if (arr == 2) src = Bh + (size_t)(n0 + r) * ldb + k0 + q * 8;
            else               src = Bl + (size_t)(n0 + r) * ldb + k0 + q * 8;
            const uint32_t dst = st + arr * 16384 + r * 128 + ((q ^ (r & 7)) << 4);
            CPA16(dst, src);
        }
        CPA_COMMIT();
    };

    load_chunk(0);
    if (nch > 1) load_chunk(1);

    for (int c = 0; c < nch; c++) {
        if (c + 2 < nch)      { load_chunk(c + 2); CPA_WAIT(2); }
        else if (c + 1 < nch) { CPA_WAIT(1); }
        else                  { CPA_WAIT(0); }
        __syncthreads();

        const uint32_t st = smb + (c % 3) * STAGE;
        const uint32_t sAh = st, sAl = st + 16384, sBh = st + 32768, sBl = st + 49152;

#pragma unroll
        for (int kk = 0; kk < 4; kk++) {
            uint32_t ahf[4][4], alf[4][4], bhf[4][2], blf[4][2];
            const int acq = kk * 2 + a_colq_l;
#pragma unroll
            for (int mi = 0; mi < 4; mi++) {
                const int r = wm + mi * 16 + a_row_l;
                const uint32_t off = r * 128 + ((acq ^ (r & 7)) << 4);
                LDSM4(ahf[mi], sAh + off);
                LDSM4(alf[mi], sAl + off);
            }
            const int bcq = kk * 2 + b_colq_l;
#pragma unroll
            for (int nj = 0; nj < 2; nj++) {
                const int r = wn + nj * 16 + b_row_l;
                const uint32_t off = r * 128 + ((bcq ^ (r & 7)) << 4);
                uint32_t t4[4];
                LDSM4(t4, sBh + off);
                bhf[nj*2][0] = t4[0]; bhf[nj*2][1] = t4[1];
                bhf[nj*2+1][0] = t4[2]; bhf[nj*2+1][1] = t4[3];
                LDSM4(t4, sBl + off);
                blf[nj*2][0] = t4[0]; blf[nj*2][1] = t4[1];
                blf[nj*2+1][0] = t4[2]; blf[nj*2+1][1] = t4[3];
            }
#pragma unroll
            for (int mi = 0; mi < 4; mi++)
#pragma unroll
                for (int ni = 0; ni < 4; ni++) {
                    MMA_BF16(acc[mi][ni], ahf[mi], bhf[ni]);
                    MMA_BF16(acc[mi][ni], ahf[mi], blf[ni]);
                    MMA_BF16(acc[mi][ni], alf[mi], bhf[ni]);
                }
        }
        __syncthreads();
    }

    const int g = lane >> 2, t = lane & 3;
#pragma unroll
    for (int mi = 0; mi < 4; mi++)
#pragma unroll
        for (int ni = 0; ni < 4; ni++)
#pragma unroll
            for (int half_ = 0; half_ < 2; half_++) {
                const int row = m0 + wm + mi * 16 + g + half_ * 8;
                const int col = n0 + wn + ni * 8 + 2 * t;
                float v0 = acc[mi][ni][half_ * 2 + 0];
                float v1 = acc[mi][ni][half_ * 2 + 1];
                if (C) *(float2*)(C + (size_t)row * ldc + col) = make_float2(v0, v1);
                if (Ch)
                    *(uint32_t*)(Ch + (size_t)row * ldc + col) =
                        pack2h(__float2half_rn(v0), __float2half_rn(v1));
            }
}

// ---------------- fp32 -> fp16 weight convert (4/thread) ----------------
__global__ void cvt4h(const float4* __restrict__ in, uint2* __restrict__ out, long long n4)
{
    long long i = (long long)blockIdx.x * blockDim.x + threadIdx.x;
    if (i >= n4) return;
    float4 v = in[i];
    out[i] = make_uint2(pack2h(__float2half_rn(v.x), __float2half_rn(v.y)),
                        pack2h(__float2half_rn(v.z), __float2half_rn(v.w)));
}

// ---------------- row l2norm -> fp16 ----------------
__global__ void l2norm_rows_h(const float* __restrict__ in, half* __restrict__ out, int cols)
{
    const int row = blockIdx.x;
    const float* x = in + (long long)row * cols;
    float s = 0.f;
    for (int c = threadIdx.x; c < cols; c += blockDim.x) { float v = x[c]; s += v * v; }
    __shared__ float red[32];
#pragma unroll
    for (int o = 16; o; o >>= 1) s += __shfl_xor_sync(0xffffffffu, s, o);
    if ((threadIdx.x & 31) == 0) red[threadIdx.x >> 5] = s;
    __syncthreads();
    const int nw = blockDim.x >> 5;
    if (threadIdx.x < 32) {
        float t = (threadIdx.x < nw) ? red[threadIdx.x] : 0.f;
#pragma unroll
        for (int o = 16; o; o >>= 1) t += __shfl_xor_sync(0xffffffffu, t, o);
        if (threadIdx.x == 0) red[0] = rsqrtf(t);
    }
    __syncthreads();
    const float r = red[0];
    for (int c = threadIdx.x; c < cols; c += blockDim.x)
        out[(long long)row * cols + c] = __float2half_rn(x[c] * r);
}

__global__ void l2norm_rows(const float* __restrict__ in, float* __restrict__ out, int cols)
{
    const int row = blockIdx.x;
    const float* x = in + (long long)row * cols;
    float* y = out + (long long)row * cols;
    float s = 0.f;
    for (int c = threadIdx.x; c < cols; c += blockDim.x) { float v = x[c]; s += v * v; }
    __shared__ float red[32];
#pragma unroll
    for (int o = 16; o; o >>= 1) s += __shfl_xor_sync(0xffffffffu, s, o);
    if ((threadIdx.x & 31) == 0) red[threadIdx.x >> 5] = s;
    __syncthreads();
    const int nw = blockDim.x >> 5;
    if (threadIdx.x < 32) {
        float t = (threadIdx.x < nw) ? red[threadIdx.x] : 0.f;
#pragma unroll
        for (int o = 16; o; o >>= 1) t += __shfl_xor_sync(0xffffffffu, t, o);
        if (threadIdx.x == 0) red[0] = rsqrtf(t);
    }
    __syncthreads();
    const float r = red[0];
    for (int c = threadIdx.x; c < cols; c += blockDim.x) y[c] = x[c] * r;
}

// ---------------- per-head norm + RoPE -> split Q/K (bf16 hi/lo) ----------------
__global__ void qk_rope_split(const float* __restrict__ qkv, const float* __restrict__ qknw,
                              const float* __restrict__ cosb, const float* __restrict__ sinb,
                              bf16* __restrict__ Qh, bf16* __restrict__ Ql,
                              bf16* __restrict__ Kh, bf16* __restrict__ Kl)
{
    const int s = blockIdx.x;
    const int h = blockIdx.y;
    const int d = threadIdx.x;
    __shared__ float sv[128];
    __shared__ float red[4];

    float v = qkv[(long long)s * QKVO + h * HD + d];
    float ss = v * v;
#pragma unroll
    for (int o = 16; o; o >>= 1) ss += __shfl_xor_sync(0xffffffffu, ss, o);
    if ((d & 31) == 0) red[d >> 5] = ss;
    __syncthreads();
    const float tot = red[0] + red[1] + red[2] + red[3];
    const float nv = v * rsqrtf(tot) * qknw[h * HD + d];
    sv[d] = nv;
    __syncthreads();
    const float rot = (d < 64) ? sv[d + 64] : sv[d - 64];
    const float ov = nv * cosb[s * HD + d] + rot * sinb[s * HD + d];
    bf16 hh, ll;
    split2(ov, hh, ll);
    if (h < NH) {
        size_t o = ((size_t)h * SEQ + s) * HD + d;
        Qh[o] = hh; Ql[o] = ll;
    } else {
        size_t o = ((size_t)(h - NH) * SEQ + s) * HD + d;
        Kh[o] = hh; Kl[o] = ll;
    }
}

// ---------------- V transpose -> split (bf16 hi/lo) ----------------
__global__ void v_transpose_split(const float* __restrict__ qkv,
                                  bf16* __restrict__ Vth, bf16* __restrict__ Vtl)
{
    __shared__ float t[32][33];
    const int h = blockIdx.z;
    const int s0 = blockIdx.x * 32;
    const int d0 = blockIdx.y * 32;
    t[threadIdx.y][threadIdx.x] =
        qkv[(long long)(s0 + threadIdx.y) * QKVO + QKH * HD + h * HD + d0 + threadIdx.x];
    __syncthreads();
    bf16 hh, ll;
    split2(t[threadIdx.x][threadIdx.y], hh, ll);
    size_t o = ((size_t)h * HD + d0 + threadIdx.y) * SEQ + s0 + threadIdx.x;
    Vth[o] = hh; Vtl[o] = ll;
}

// ---------------- causal softmax (K-limited) -> split probs (bf16) ----------------
__global__ void softmax_causal_split(const float* __restrict__ scores, const float* __restrict__ maskp,
                                     bf16* __restrict__ Ph, bf16* __restrict__ Pl)
{
    const int q = blockIdx.x;
    const int h = blockIdx.y;
    const int kmax = ((q >> 7) + 1) << 7;
    const float* row = scores + ((long long)h * SEQ + q) * SEQ;
    const float mpen = -128.f * maskp[0];
    const int tid = threadIdx.x;

    float vals[4];
    float mx = -1e30f;
#pragma unroll
    for (int i = 0; i < 4; i++) {
        int k = tid + i * 256;
        if (k < kmax) {
            float v = row[k] + (k > q ? mpen : 0.f);
            vals[i] = v;
            mx = fmaxf(mx, v);
        } else vals[i] = -1e30f;
    }
    __shared__ float redm[8];
    __shared__ float reds[8];
#pragma unroll
    for (int o = 16; o; o >>= 1) mx = fmaxf(mx, __shfl_xor_sync(0xffffffffu, mx, o));
    if ((tid & 31) == 0) redm[tid >> 5] = mx;
    __syncthreads();
    if (tid < 32) {
        float m2 = (tid < 8) ? redm[tid] : -1e30f;
#pragma unroll
        for (int o = 16; o; o >>= 1) m2 = fmaxf(m2, __shfl_xor_sync(0xffffffffu, m2, o));
        if (tid == 0) redm[0] = m2;
    }
    __syncthreads();
    mx = redm[0];

    float s = 0.f;
#pragma unroll
    for (int i = 0; i < 4; i++) {
        int k = tid + i * 256;
        if (k < kmax) { vals[i] = expf(vals[i] - mx); s += vals[i]; }
    }
#pragma unroll
    for (int o = 16; o; o >>= 1) s += __shfl_xor_sync(0xffffffffu, s, o);
    if ((tid & 31) == 0) reds[tid >> 5] = s;
    __syncthreads();
    if (tid < 32) {
        float t2 = (tid < 8) ? reds[tid] : 0.f;
#pragma unroll
        for (int o = 16; o; o >>= 1) t2 += __shfl_xor_sync(0xffffffffu, t2, o);
        if (tid == 0) reds[0] = 1.f / t2;
    }
    __syncthreads();
    const float inv = reds[0];
    const size_t base = ((size_t)h * SEQ + q) * SEQ;
#pragma unroll
    for (int i = 0; i < 4; i++) {
        int k = tid + i * 256;
        if (k < kmax) {
            bf16 hh, ll;
            split2(vals[i] * inv, hh, ll);
            Ph[base + k] = hh;
            Pl[base + k] = ll;
        }
    }
}

// ---------------- SwiGLU -> fp16 ----------------
__global__ void silu_mul_h(const float* __restrict__ gu, half* __restrict__ act)
{
    const long long i = (long long)blockIdx.x * blockDim.x + threadIdx.x;
    const int s = (int)(i / DFF);
    const int f = (int)(i % DFF);
    const float g = gu[(long long)s * (2 * DFF) + f];
    const float u = gu[(long long)s * (2 * DFF) + DFF + f];
    act[i] = __float2half_rn((g / (1.f + expf(-g))) * u);
}

// ---------------- lm_head GEMV (fp32) ----------------
__global__ void lm_head(const float* __restrict__ last, const float* __restrict__ W,
                        float* __restrict__ out)
{
    const int warp = threadIdx.x >> 5;
    const int lane = threadIdx.x & 31;
    const int v = blockIdx.x * 8 + warp;
    const float* w = W + (long long)v * HDIM;
    float s = 0.f;
#pragma unroll
    for (int j = lane * 4; j < HDIM; j += 128) {
        float4 wv = *(const float4*)(w + j);
        float4 lv = *(const float4*)(last + j);
        s += wv.x * lv.x + wv.y * lv.y + wv.z * lv.z + wv.w * lv.w;
    }
#pragma unroll
    for (int o = 16; o; o >>= 1) s += __shfl_xor_sync(0xffffffffu, s, o);
    if (lane == 0) out[v] = s;
}

// ---------------- launcher ----------------
extern "C" void kernel_launch(void* const* d_in, const int* in_sizes, int n_in,
                              void* d_out, int out_size)
{
    const float* hidden = (const float*)d_in[0];
    const float* qkv_w  = (const float*)d_in[1];
    const float* qknw   = (const float*)d_in[2];
    const float* o_w    = (const float*)d_in[3];
    const float* gu_w   = (const float*)d_in[4];
    const float* dn_w   = (const float*)d_in[5];
    const float* lm_w   = (const float*)d_in[6];
    const float* cosb   = (const float*)d_in[7];
    const float* sinb   = (const float*)d_in[8];
    const float* maskp  = (const float*)d_in[9];
    float* outp = (float*)d_out;

    const int SM1 = 3 * 32768 + 1024;     // 99328  -> 2 CTAs/SM
    const int SM3 = 3 * 65536 + 1024;     // 197632 -> 1 CTA/SM
    cudaFuncSetAttribute(hgemm1, cudaFuncAttributeMaxDynamicSharedMemorySize, SM1);
    cudaFuncSetAttribute(hgemm3, cudaFuncAttributeMaxDynamicSharedMemorySize, SM3);

    float *px, *pqkv, *psc, *pgu, *plast;
    half *phnf, *pwhf, *ppaof, *pactf;
    bf16 *pqh, *pql, *pkh, *pkl, *pvth, *pvtl, *pph, *ppl;
    cudaGetSymbolAddress((void**)&px,    g_x);
    cudaGetSymbolAddress((void**)&phnf,  g_hnf);
    cudaGetSymbolAddress((void**)&pwhf,  g_whf);
    cudaGetSymbolAddress((void**)&pqkv,  g_qkv);
    cudaGetSymbolAddress((void**)&pqh,   g_qh);
    cudaGetSymbolAddress((void**)&pql,   g_ql);
    cudaGetSymbolAddress((void**)&pkh,   g_kh);
    cudaGetSymbolAddress((void**)&pkl,   g_kl);
    cudaGetSymbolAddress((void**)&pvth,  g_vth);
    cudaGetSymbolAddress((void**)&pvtl,  g_vtl);
    cudaGetSymbolAddress((void**)&psc,   g_sc);
    cudaGetSymbolAddress((void**)&pph,   g_ph);
    cudaGetSymbolAddress((void**)&ppl,   g_pl);
    cudaGetSymbolAddress((void**)&ppaof, g_paof);
    cudaGetSymbolAddress((void**)&pgu,   g_gu);
    cudaGetSymbolAddress((void**)&pactf, g_actf);
    cudaGetSymbolAddress((void**)&plast, g_last);

    const float* xin = hidden;

    for (int l = 0; l < NLAY; l++) {
        l2norm_rows_h<<<SEQ, 256>>>(xin, phnf, HDIM);

        // QKV projection (fp16 single-term)
        {
            long long n4 = (long long)QKVO * HDIM / 4;
            cvt4h<<<(unsigned)((n4 + 255) / 256), 256>>>(
                (const float4*)(qkv_w + (long long)l * QKVO * HDIM), (uint2*)pwhf, n4);
        }
        hgemm1<<<dim3(SEQ / 128, QKVO / 128), 256, SM1>>>(
            phnf, HDIM, pwhf, HDIM, pqkv, QKVO, HDIM, nullptr, 0);

        qk_rope_split<<<dim3(SEQ, QKH), 128>>>(pqkv, qknw + (long long)l * QKH * HD,
                                               cosb, sinb, pqh, pql, pkh, pkl);
        v_transpose_split<<<dim3(SEQ / 32, HD / 32, KVH), dim3(32, 32)>>>(pqkv, pvth, pvtl);

        // scores = Q K^T per head (bf16 3-term, causal tile skip)
        hgemm3<<<dim3(SEQ / 128, SEQ / 128, NH), 256, SM3>>>(
            pqh, pql, HD, pkh, pkl, HD, psc, nullptr, SEQ, HD,
            (long long)SEQ * HD, (long long)SEQ * HD, (long long)SEQ * SEQ, 1, 1);

        softmax_causal_split<<<dim3(SEQ, NH), 256>>>(psc, maskp, pph, ppl);

        // out = P V (bf16 3-term, K-limited; fp16 output slab)
        hgemm3<<<dim3(SEQ / 128, 1, NH), 256, SM3>>>(
            pph, ppl, SEQ, pvth, pvtl, SEQ, nullptr, ppaof, HDIM, SEQ,
            (long long)SEQ * SEQ, (long long)HD * SEQ, (long long)HD, 1, 2);

        // O projection + residual (fp16 single-term)
        {
            long long n4 = (long long)HDIM * HDIM / 4;
            cvt4h<<<(unsigned)((n4 + 255) / 256), 256>>>(
                (const float4*)(o_w + (long long)l * HDIM * HDIM), (uint2*)pwhf, n4);
        }
        hgemm1<<<dim3(SEQ / 128, HDIM / 128), 256, SM1>>>(
            ppaof, HDIM, pwhf, HDIM, px, HDIM, HDIM, xin, HDIM);

        // MLP (fp16 single-term)
        l2norm_rows_h<<<SEQ, 256>>>(px, phnf, HDIM);
        {
            long long n4 = (long long)2 * DFF * HDIM / 4;
            cvt4h<<<(unsigned)((n4 + 255) / 256), 256>>>(
                (const float4*)(gu_w + (long long)l * 2 * DFF * HDIM), (uint2*)pwhf, n4);
        }
        hgemm1<<<dim3(SEQ / 128, 2 * DFF / 128), 256, SM1>>>(
            phnf, HDIM, pwhf, HDIM, pgu, 2 * DFF, HDIM, nullptr, 0);
        silu_mul_h<<<(SEQ * DFF) / 256, 256>>>(pgu, pactf);
        {
            long long n4 = (long long)HDIM * DFF / 4;
            cvt4h<<<(unsigned)((n4 + 255) / 256), 256>>>(
                (const float4*)(dn_w + (long long)l * HDIM * DFF), (uint2*)pwhf, n4);
        }
        hgemm1<<<dim3(SEQ / 128, HDIM / 128), 256, SM1>>>(
            pactf, DFF, pwhf, DFF, px, HDIM, DFF, px, HDIM);

        xin = px;
    }

    l2norm_rows<<<1, 256>>>(px + (long long)(SEQ - 1) * HDIM, plast, HDIM);
    lm_head<<<VOC / 8, 256>>>(plast, lm_w, outp);
}

// round 7
// speedup vs baseline: 6.3624x; 1.0634x over previous
#include <cuda_runtime.h>
#include <cuda_fp16.h>
#include <stdint.h>
#include <math.h>

#define SEQ   1024
#define HDIM  2048
#define NH    16
#define KVH   8
#define HD    128
#define QKH   24
#define QKVO  4096
#define DFF   6144
#define VOC   32000
#define NLAY  2

// ---------------- device scratch (no allocs allowed) ----------------
__device__ __align__(16) float g_x   [SEQ*HDIM];
__device__ __align__(16) half  g_hnf [SEQ*HDIM];
__device__ __align__(16) half  g_whf [2*DFF*HDIM];
__device__ __align__(16) float g_qkv [SEQ*QKVO];
__device__ __align__(16) half  g_qf  [NH*SEQ*HD];
__device__ __align__(16) half  g_kf  [KVH*SEQ*HD];
__device__ __align__(16) half  g_vtf [KVH*HD*SEQ];
__device__ __align__(16) float g_sc  [NH*SEQ*SEQ];
__device__ __align__(16) half  g_pf  [NH*SEQ*SEQ];
__device__ __align__(16) half  g_paof[SEQ*HDIM];
__device__ __align__(16) float g_gu  [SEQ*2*DFF];
__device__ __align__(16) half  g_actf[SEQ*DFF];
__device__ __align__(16) float g_last[HDIM];

// ---------------- helpers ----------------
__device__ __forceinline__ uint32_t smem_u32(const void* p) {
    uint32_t a;
    asm("{ .reg .u64 t; cvta.to.shared.u64 t, %1; cvt.u32.u64 %0, t; }" : "=r"(a) : "l"(p));
    return a;
}
__device__ __forceinline__ uint32_t pack2h(half a, half b) {
    return (uint32_t)__half_as_ushort(a) | ((uint32_t)__half_as_ushort(b) << 16);
}

#define CPA16(d, s) asm volatile("cp.async.cg.shared.global [%0], [%1], 16;" :: "r"(d), "l"(s))
#define CPA_COMMIT() asm volatile("cp.async.commit_group;" ::: "memory")
#define CPA_WAIT(n)  asm volatile("cp.async.wait_group %0;" :: "n"(n) : "memory")

#define LDSM4(r, a) \
    asm volatile("ldmatrix.sync.aligned.m8n8.x4.shared.b16 {%0,%1,%2,%3}, [%4];" \
        : "=r"((r)[0]), "=r"((r)[1]), "=r"((r)[2]), "=r"((r)[3]) : "r"(a))

#define MMA_F16(c, a, b) \
    asm volatile("mma.sync.aligned.m16n8k16.row.col.f32.f16.f16.f32 " \
        "{%0,%1,%2,%3}, {%4,%5,%6,%7}, {%8,%9}, {%0,%1,%2,%3};" \
        : "+f"((c)[0]), "+f"((c)[1]), "+f"((c)[2]), "+f"((c)[3]) \
        : "r"((a)[0]), "r"((a)[1]), "r"((a)[2]), "r"((a)[3]), "r"((b)[0]), "r"((b)[1]))

// ============================================================================
// Unified fp16 GEMM (NT): C[z] = A[z](MxK) * B[z>>shift](NxK)^T (+resid)
// 128x128 tile, 3-stage cp.async (32KB stages), 2 CTAs/SM.
// causal bit0: skip n0>m0 tiles (scores). bit1: K-limit to m0+128 (PV).
// Output: fp32 Cf and/or fp16 Ch.
// ============================================================================
__global__ __launch_bounds__(256, 2)
void hgemm(const half* __restrict__ A, int lda,
           const half* __restrict__ B, int ldb,
           float* __restrict__ Cf, half* __restrict__ Ch, int ldc, int K,
           const float* __restrict__ resid, int ldr,
           long long bsA, long long bsB, long long bsC, int bShiftB, int causal)
{
    constexpr int STG = 32768;
    extern __shared__ char dynraw[];
    char* sm = (char*)(((uintptr_t)dynraw + 1023) & ~(uintptr_t)1023);
    const uint32_t smb = smem_u32(sm);

    const int m0 = blockIdx.x * 128;
    const int n0 = blockIdx.y * 128;
    if ((causal & 1) && n0 > m0) return;

    const int tid  = threadIdx.x;
    const int lane = tid & 31;
    const int wid  = tid >> 5;
    const int wm   = (wid >> 2) * 64;
    const int wn   = (wid & 3) * 32;

    const long long z = blockIdx.z;
    A += z * bsA;
    B += (z >> bShiftB) * bsB;
    if (Cf) Cf += z * bsC;
    if (Ch) Ch += z * bsC;

    const int Keff = (causal & 2) ? min(K, m0 + 128) : K;
    const int nch  = Keff >> 6;

    const int a_row_l  = lane & 15;
    const int a_colq_l = lane >> 4;
    const int b_row_l  = (lane & 7) + ((lane & 16) >> 1);
    const int b_colq_l = (lane >> 3) & 1;

    float acc[4][4][4];
#pragma unroll
    for (int i = 0; i < 4; i++)
#pragma unroll
        for (int j = 0; j < 4; j++)
#pragma unroll
            for (int q = 0; q < 4; q++) acc[i][j][q] = 0.f;

    auto load_chunk = [&](int c) {
        const int k0 = c << 6;
        const uint32_t st = smb + (c % 3) * STG;
#pragma unroll
        for (int it = 0; it < 8; it++) {
            const int g   = it * 256 + tid;
            const int arr = it >> 2;
            const int r   = (g >> 3) & 127;
            const int q   = g & 7;
            const half* src = arr ? (B + (size_t)(n0 + r) * ldb + k0 + q * 8)
                                  : (A + (size_t)(m0 + r) * lda + k0 + q * 8);
            const uint32_t dst = st + arr * 16384 + r * 128 + ((q ^ (r & 7)) << 4);
            CPA16(dst, src);
        }
        CPA_COMMIT();
    };

    load_chunk(0);
    if (nch > 1) load_chunk(1);

    for (int c = 0; c < nch; c++) {
        if (c + 2 < nch)      { load_chunk(c + 2); CPA_WAIT(2); }
        else if (c + 1 < nch) { CPA_WAIT(1); }
        else                  { CPA_WAIT(0); }
        __syncthreads();

        const uint32_t st = smb + (c % 3) * STG;
        const uint32_t sA = st, sB = st + 16384;

#pragma unroll
        for (int kk = 0; kk < 4; kk++) {
            uint32_t af[4][4], bfr[4][2];
            const int acq = kk * 2 + a_colq_l;
#pragma unroll
            for (int mi = 0; mi < 4; mi++) {
                const int r = wm + mi * 16 + a_row_l;
                LDSM4(af[mi], sA + r * 128 + ((acq ^ (r & 7)) << 4));
            }
            const int bcq = kk * 2 + b_colq_l;
#pragma unroll
            for (int nj = 0; nj < 2; nj++) {
                const int r = wn + nj * 16 + b_row_l;
                uint32_t t4[4];
                LDSM4(t4, sB + r * 128 + ((bcq ^ (r & 7)) << 4));
                bfr[nj*2][0] = t4[0]; bfr[nj*2][1] = t4[1];
                bfr[nj*2+1][0] = t4[2]; bfr[nj*2+1][1] = t4[3];
            }
#pragma unroll
            for (int mi = 0; mi < 4; mi++)
#pragma unroll
                for (int ni = 0; ni < 4; ni++)
                    MMA_F16(acc[mi][ni], af[mi], bfr[ni]);
        }
        __syncthreads();
    }

    const int g = lane >> 2, t = lane & 3;
#pragma unroll
    for (int mi = 0; mi < 4; mi++)
#pragma unroll
        for (int ni = 0; ni < 4; ni++)
#pragma unroll
            for (int h2 = 0; h2 < 2; h2++) {
                const int row = m0 + wm + mi * 16 + g + h2 * 8;
                const int col = n0 + wn + ni * 8 + 2 * t;
                float v0 = acc[mi][ni][h2 * 2 + 0];
                float v1 = acc[mi][ni][h2 * 2 + 1];
                if (resid) {
                    const float* rp = resid + (size_t)row * ldr + col;
                    v0 += rp[0]; v1 += rp[1];
                }
                if (Cf) *(float2*)(Cf + (size_t)row * ldc + col) = make_float2(v0, v1);
                if (Ch)
                    *(uint32_t*)(Ch + (size_t)row * ldc + col) =
                        pack2h(__float2half_rn(v0), __float2half_rn(v1));
            }
}

// ---------------- fp32 -> fp16 convert (4/thread) ----------------
__global__ void cvt4h(const float4* __restrict__ in, uint2* __restrict__ out, long long n4)
{
    long long i = (long long)blockIdx.x * blockDim.x + threadIdx.x;
    if (i >= n4) return;
    float4 v = in[i];
    out[i] = make_uint2(pack2h(__float2half_rn(v.x), __float2half_rn(v.y)),
                        pack2h(__float2half_rn(v.z), __float2half_rn(v.w)));
}

// ---------------- row l2norm -> fp16 ----------------
__global__ void l2norm_rows_h(const float* __restrict__ in, half* __restrict__ out, int cols)
{
    const int row = blockIdx.x;
    const float* x = in + (long long)row * cols;
    float s = 0.f;
    for (int c = threadIdx.x; c < cols; c += blockDim.x) { float v = x[c]; s += v * v; }
    __shared__ float red[32];
#pragma unroll
    for (int o = 16; o; o >>= 1) s += __shfl_xor_sync(0xffffffffu, s, o);
    if ((threadIdx.x & 31) == 0) red[threadIdx.x >> 5] = s;
    __syncthreads();
    const int nw = blockDim.x >> 5;
    if (threadIdx.x < 32) {
        float t = (threadIdx.x < nw) ? red[threadIdx.x] : 0.f;
#pragma unroll
        for (int o = 16; o; o >>= 1) t += __shfl_xor_sync(0xffffffffu, t, o);
        if (threadIdx.x == 0) red[0] = rsqrtf(t);
    }
    __syncthreads();
    const float r = red[0];
    for (int c = threadIdx.x; c < cols; c += blockDim.x)
        out[(long long)row * cols + c] = __float2half_rn(x[c] * r);
}

__global__ void l2norm_rows(const float* __restrict__ in, float* __restrict__ out, int cols)
{
    const int row = blockIdx.x;
    const float* x = in + (long long)row * cols;
    float* y = out + (long long)row * cols;
    float s = 0.f;
    for (int c = threadIdx.x; c < cols; c += blockDim.x) { float v = x[c]; s += v * v; }
    __shared__ float red[32];
#pragma unroll
    for (int o = 16; o; o >>= 1) s += __shfl_xor_sync(0xffffffffu, s, o);
    if ((threadIdx.x & 31) == 0) red[threadIdx.x >> 5] = s;
    __syncthreads();
    const int nw = blockDim.x >> 5;
    if (threadIdx.x < 32) {
        float t = (threadIdx.x < nw) ? red[threadIdx.x] : 0.f;
#pragma unroll
        for (int o = 16; o; o >>= 1) t += __shfl_xor_sync(0xffffffffu, t, o);
        if (threadIdx.x == 0) red[0] = rsqrtf(t);
    }
    __syncthreads();
    const float r = red[0];
    for (int c = threadIdx.x; c < cols; c += blockDim.x) y[c] = x[c] * r;
}

// ---------------- per-head norm + RoPE -> fp16 Q/K ----------------
__global__ void qk_rope_h(const float* __restrict__ qkv, const float* __restrict__ qknw,
                          const float* __restrict__ cosb, const float* __restrict__ sinb,
                          half* __restrict__ Q, half* __restrict__ Kb)
{
    const int s = blockIdx.x;
    const int h = blockIdx.y;
    const int d = threadIdx.x;
    __shared__ float sv[128];
    __shared__ float red[4];

    float v = qkv[(long long)s * QKVO + h * HD + d];
    float ss = v * v;
#pragma unroll
    for (int o = 16; o; o >>= 1) ss += __shfl_xor_sync(0xffffffffu, ss, o);
    if ((d & 31) == 0) red[d >> 5] = ss;
    __syncthreads();
    const float tot = red[0] + red[1] + red[2] + red[3];
    const float nv = v * rsqrtf(tot) * qknw[h * HD + d];
    sv[d] = nv;
    __syncthreads();
    const float rot = (d < 64) ? sv[d + 64] : sv[d - 64];
    const half ov = __float2half_rn(nv * cosb[s * HD + d] + rot * sinb[s * HD + d]);
    if (h < NH) Q[((size_t)h * SEQ + s) * HD + d] = ov;
    else        Kb[((size_t)(h - NH) * SEQ + s) * HD + d] = ov;
}

// ---------------- V transpose -> fp16 ----------------
__global__ void v_transpose_h(const float* __restrict__ qkv, half* __restrict__ Vt)
{
    __shared__ float t[32][33];
    const int h = blockIdx.z;
    const int s0 = blockIdx.x * 32;
    const int d0 = blockIdx.y * 32;
    t[threadIdx.y][threadIdx.x] =
        qkv[(long long)(s0 + threadIdx.y) * QKVO + QKH * HD + h * HD + d0 + threadIdx.x];
    __syncthreads();
    Vt[((size_t)h * HD + d0 + threadIdx.y) * SEQ + s0 + threadIdx.x] =
        __float2half_rn(t[threadIdx.x][threadIdx.y]);
}

// ---------------- causal softmax (K-limited) -> fp16 probs ----------------
__global__ void softmax_causal_h(const float* __restrict__ scores, const float* __restrict__ maskp,
                                 half* __restrict__ P)
{
    const int q = blockIdx.x;
    const int h = blockIdx.y;
    const int kmax = ((q >> 7) + 1) << 7;
    const float* row = scores + ((long long)h * SEQ + q) * SEQ;
    const float mpen = -128.f * maskp[0];
    const int tid = threadIdx.x;

    float vals[4];
    float mx = -1e30f;
#pragma unroll
    for (int i = 0; i < 4; i++) {
        int k = tid + i * 256;
        if (k < kmax) {
            float v = row[k] + (k > q ? mpen : 0.f);
            vals[i] = v;
            mx = fmaxf(mx, v);
        } else vals[i] = -1e30f;
    }
    __shared__ float redm[8];
    __shared__ float reds[8];
#pragma unroll
    for (int o = 16; o; o >>= 1) mx = fmaxf(mx, __shfl_xor_sync(0xffffffffu, mx, o));
    if ((tid & 31) == 0) redm[tid >> 5] = mx;
    __syncthreads();
    if (tid < 32) {
        float m2 = (tid < 8) ? redm[tid] : -1e30f;
#pragma unroll
        for (int o = 16; o; o >>= 1) m2 = fmaxf(m2, __shfl_xor_sync(0xffffffffu, m2, o));
        if (tid == 0) redm[0] = m2;
    }
    __syncthreads();
    mx = redm[0];

    float s = 0.f;
#pragma unroll
    for (int i = 0; i < 4; i++) {
        int k = tid + i * 256;
        if (k < kmax) { vals[i] = expf(vals[i] - mx); s += vals[i]; }
    }
#pragma unroll
    for (int o = 16; o; o >>= 1) s += __shfl_xor_sync(0xffffffffu, s, o);
    if ((tid & 31) == 0) reds[tid >> 5] = s;
    __syncthreads();
    if (tid < 32) {
        float t2 = (tid < 8) ? reds[tid] : 0.f;
#pragma unroll
        for (int o = 16; o; o >>= 1) t2 += __shfl_xor_sync(0xffffffffu, t2, o);
        if (tid == 0) reds[0] = 1.f / t2;
    }
    __syncthreads();
    const float inv = reds[0];
    const size_t base = ((size_t)h * SEQ + q) * SEQ;
#pragma unroll
    for (int i = 0; i < 4; i++) {
        int k = tid + i * 256;
        if (k < kmax) P[base + k] = __float2half_rn(vals[i] * inv);
    }
}

// ---------------- SwiGLU -> fp16 ----------------
__global__ void silu_mul_h(const float* __restrict__ gu, half* __restrict__ act)
{
    const long long i = (long long)blockIdx.x * blockDim.x + threadIdx.x;
    const int s = (int)(i / DFF);
    const int f = (int)(i % DFF);
    const float g = gu[(long long)s * (2 * DFF) + f];
    const float u = gu[(long long)s * (2 * DFF) + DFF + f];
    act[i] = __float2half_rn((g / (1.f + expf(-g))) * u);
}

// ---------------- lm_head GEMV (fp32) ----------------
__global__ void lm_head(const float* __restrict__ last, const float* __restrict__ W,
                        float* __restrict__ out)
{
    const int warp = threadIdx.x >> 5;
    const int lane = threadIdx.x & 31;
    const int v = blockIdx.x * 8 + warp;
    const float* w = W + (long long)v * HDIM;
    float s = 0.f;
#pragma unroll
    for (int j = lane * 4; j < HDIM; j += 128) {
        float4 wv = *(const float4*)(w + j);
        float4 lv = *(const float4*)(last + j);
        s += wv.x * lv.x + wv.y * lv.y + wv.z * lv.z + wv.w * lv.w;
    }
#pragma unroll
    for (int o = 16; o; o >>= 1) s += __shfl_xor_sync(0xffffffffu, s, o);
    if (lane == 0) out[v] = s;
}

// ---------------- launcher ----------------
extern "C" void kernel_launch(void* const* d_in, const int* in_sizes, int n_in,
                              void* d_out, int out_size)
{
    const float* hidden = (const float*)d_in[0];
    const float* qkv_w  = (const float*)d_in[1];
    const float* qknw   = (const float*)d_in[2];
    const float* o_w    = (const float*)d_in[3];
    const float* gu_w   = (const float*)d_in[4];
    const float* dn_w   = (const float*)d_in[5];
    const float* lm_w   = (const float*)d_in[6];
    const float* cosb   = (const float*)d_in[7];
    const float* sinb   = (const float*)d_in[8];
    const float* maskp  = (const float*)d_in[9];
    float* outp = (float*)d_out;

    const int SMB = 3 * 32768 + 1024;   // 99328 -> 2 CTAs/SM
    cudaFuncSetAttribute(hgemm, cudaFuncAttributeMaxDynamicSharedMemorySize, SMB);

    float *px, *pqkv, *psc, *pgu, *plast;
    half *phnf, *pwhf, *pqf, *pkf, *pvtf, *ppf, *ppaof, *pactf;
    cudaGetSymbolAddress((void**)&px,    g_x);
    cudaGetSymbolAddress((void**)&phnf,  g_hnf);
    cudaGetSymbolAddress((void**)&pwhf,  g_whf);
    cudaGetSymbolAddress((void**)&pqkv,  g_qkv);
    cudaGetSymbolAddress((void**)&pqf,   g_qf);
    cudaGetSymbolAddress((void**)&pkf,   g_kf);
    cudaGetSymbolAddress((void**)&pvtf,  g_vtf);
    cudaGetSymbolAddress((void**)&psc,   g_sc);
    cudaGetSymbolAddress((void**)&ppf,   g_pf);
    cudaGetSymbolAddress((void**)&ppaof, g_paof);
    cudaGetSymbolAddress((void**)&pgu,   g_gu);
    cudaGetSymbolAddress((void**)&pactf, g_actf);
    cudaGetSymbolAddress((void**)&plast, g_last);

    const float* xin = hidden;

    for (int l = 0; l < NLAY; l++) {
        l2norm_rows_h<<<SEQ, 256>>>(xin, phnf, HDIM);

        // QKV projection
        {
            long long n4 = (long long)QKVO * HDIM / 4;
            cvt4h<<<(unsigned)((n4 + 255) / 256), 256>>>(
                (const float4*)(qkv_w + (long long)l * QKVO * HDIM), (uint2*)pwhf, n4);
        }
        hgemm<<<dim3(SEQ / 128, QKVO / 128, 1), 256, SMB>>>(
            phnf, HDIM, pwhf, HDIM, pqkv, nullptr, QKVO, HDIM,
            nullptr, 0, 0, 0, 0, 0, 0);

        qk_rope_h<<<dim3(SEQ, QKH), 128>>>(pqkv, qknw + (long long)l * QKH * HD,
                                           cosb, sinb, pqf, pkf);
        v_transpose_h<<<dim3(SEQ / 32, HD / 32, KVH), dim3(32, 32)>>>(pqkv, pvtf);

        // scores = Q K^T per head (causal tile skip)
        hgemm<<<dim3(SEQ / 128, SEQ / 128, NH), 256, SMB>>>(
            pqf, HD, pkf, HD, psc, nullptr, SEQ, HD,
            nullptr, 0,
            (long long)SEQ * HD, (long long)SEQ * HD, (long long)SEQ * SEQ, 1, 1);

        softmax_causal_h<<<dim3(SEQ, NH), 256>>>(psc, maskp, ppf);

        // out = P V (K-limited; fp16 output slab per head)
        hgemm<<<dim3(SEQ / 128, 1, NH), 256, SMB>>>(
            ppf, SEQ, pvtf, SEQ, nullptr, ppaof, HDIM, SEQ,
            nullptr, 0,
            (long long)SEQ * SEQ, (long long)HD * SEQ, (long long)HD, 1, 2);

        // O projection + residual
        {
            long long n4 = (long long)HDIM * HDIM / 4;
            cvt4h<<<(unsigned)((n4 + 255) / 256), 256>>>(
                (const float4*)(o_w + (long long)l * HDIM * HDIM), (uint2*)pwhf, n4);
        }
        hgemm<<<dim3(SEQ / 128, HDIM / 128, 1), 256, SMB>>>(
            ppaof, HDIM, pwhf, HDIM, px, nullptr, HDIM, HDIM,
            xin, HDIM, 0, 0, 0, 0, 0);

        // MLP
        l2norm_rows_h<<<SEQ, 256>>>(px, phnf, HDIM);
        {
            long long n4 = (long long)2 * DFF * HDIM / 4;
            cvt4h<<<(unsigned)((n4 + 255) / 256), 256>>>(
                (const float4*)(gu_w + (long long)l * 2 * DFF * HDIM), (uint2*)pwhf, n4);
        }
        hgemm<<<dim3(SEQ / 128, 2 * DFF / 128, 1), 256, SMB>>>(
            phnf, HDIM, pwhf, HDIM, pgu, nullptr, 2 * DFF, HDIM,
            nullptr, 0, 0, 0, 0, 0, 0);
        silu_mul_h<<<(SEQ * DFF) / 256, 256>>>(pgu, pactf);
        {
            long long n4 = (long long)HDIM * DFF / 4;
            cvt4h<<<(unsigned)((n4 + 255) / 256), 256>>>(
                (const float4*)(dn_w + (long long)l * HDIM * DFF), (uint2*)pwhf, n4);
        }
        hgemm<<<dim3(SEQ / 128, HDIM / 128, 1), 256, SMB>>>(
            pactf, DFF, pwhf, DFF, px, nullptr, HDIM, DFF,
            px, HDIM, 0, 0, 0, 0, 0);

        xin = px;
    }

    l2norm_rows<<<1, 256>>>(px + (long long)(SEQ - 1) * HDIM, plast, HDIM);
    lm_head<<<VOC / 8, 256>>>(plast, lm_w, outp);
}

// round 8
// speedup vs baseline: 6.6133x; 1.0394x over previous
#include <cuda_runtime.h>
#include <cuda_fp16.h>
#include <stdint.h>
#include <math.h>

#define SEQ   1024
#define HDIM  2048
#define NH    16
#define KVH   8
#define HD    128
#define QKH   24
#define QKVO  4096
#define DFF   6144
#define VOC   32000
#define NLAY  2

// ---------------- device scratch (no allocs allowed) ----------------
__device__ __align__(16) float g_x   [SEQ*HDIM];
__device__ __align__(16) half  g_hnf [SEQ*HDIM];
__device__ __align__(16) half  g_whf [2*DFF*HDIM];
__device__ __align__(16) float g_qkv [SEQ*QKVO];
__device__ __align__(16) half  g_qf  [NH*SEQ*HD];
__device__ __align__(16) half  g_kf  [KVH*SEQ*HD];
__device__ __align__(16) half  g_vtf [KVH*HD*SEQ];
__device__ __align__(16) half  g_scf [NH*SEQ*SEQ];     // fp16 scores
__device__ __align__(16) half  g_pf  [NH*SEQ*SEQ];     // fp16 probs
__device__ __align__(16) half  g_paof[SEQ*HDIM];
__device__ __align__(16) float g_gu  [SEQ*2*DFF];
__device__ __align__(16) half  g_actf[SEQ*DFF];
__device__ __align__(16) float g_last[HDIM];

// ---------------- helpers ----------------
__device__ __forceinline__ uint32_t smem_u32(const void* p) {
    uint32_t a;
    asm("{ .reg .u64 t; cvta.to.shared.u64 t, %1; cvt.u32.u64 %0, t; }" : "=r"(a) : "l"(p));
    return a;
}
__device__ __forceinline__ uint32_t pack2h(half a, half b) {
    return (uint32_t)__half_as_ushort(a) | ((uint32_t)__half_as_ushort(b) << 16);
}

#define CPA16(d, s) asm volatile("cp.async.cg.shared.global [%0], [%1], 16;" :: "r"(d), "l"(s))
#define CPA_COMMIT() asm volatile("cp.async.commit_group;" ::: "memory")
#define CPA_WAIT(n)  asm volatile("cp.async.wait_group %0;" :: "n"(n) : "memory")

#define LDSM4(r, a) \
    asm volatile("ldmatrix.sync.aligned.m8n8.x4.shared.b16 {%0,%1,%2,%3}, [%4];" \
        : "=r"((r)[0]), "=r"((r)[1]), "=r"((r)[2]), "=r"((r)[3]) : "r"(a))

#define MMA_F16(c, a, b) \
    asm volatile("mma.sync.aligned.m16n8k16.row.col.f32.f16.f16.f32 " \
        "{%0,%1,%2,%3}, {%4,%5,%6,%7}, {%8,%9}, {%0,%1,%2,%3};" \
        : "+f"((c)[0]), "+f"((c)[1]), "+f"((c)[2]), "+f"((c)[3]) \
        : "r"((a)[0]), "r"((a)[1]), "r"((a)[2]), "r"((a)[3]), "r"((b)[0]), "r"((b)[1]))

// ============================================================================
// Unified fp16 GEMM (NT): C[z] = A[z](MxK) * B[z>>shift](NxK)^T (+resid)
// 128x128 tile, 3-stage cp.async, ONE barrier per chunk.
// causal bit0: skip n0>m0 tiles. bit1: K-limit to m0+128.
// ============================================================================
__global__ __launch_bounds__(256, 2)
void hgemm(const half* __restrict__ A, int lda,
           const half* __restrict__ B, int ldb,
           float* __restrict__ Cf, half* __restrict__ Ch, int ldc, int K,
           const float* __restrict__ resid, int ldr,
           long long bsA, long long bsB, long long bsC, int bShiftB, int causal)
{
    constexpr int STG = 32768;
    extern __shared__ char dynraw[];
    char* sm = (char*)(((uintptr_t)dynraw + 1023) & ~(uintptr_t)1023);
    const uint32_t smb = smem_u32(sm);

    const int m0 = blockIdx.x * 128;
    const int n0 = blockIdx.y * 128;
    if ((causal & 1) && n0 > m0) return;

    const int tid  = threadIdx.x;
    const int lane = tid & 31;
    const int wid  = tid >> 5;
    const int wm   = (wid >> 2) * 64;
    const int wn   = (wid & 3) * 32;

    const long long z = blockIdx.z;
    A += z * bsA;
    B += (z >> bShiftB) * bsB;
    if (Cf) Cf += z * bsC;
    if (Ch) Ch += z * bsC;

    const int Keff = (causal & 2) ? min(K, m0 + 128) : K;
    const int nch  = Keff >> 6;

    const int a_row_l  = lane & 15;
    const int a_colq_l = lane >> 4;
    const int b_row_l  = (lane & 7) + ((lane & 16) >> 1);
    const int b_colq_l = (lane >> 3) & 1;

    float acc[4][4][4];
#pragma unroll
    for (int i = 0; i < 4; i++)
#pragma unroll
        for (int j = 0; j < 4; j++)
#pragma unroll
            for (int q = 0; q < 4; q++) acc[i][j][q] = 0.f;

    auto load_chunk = [&](int c) {
        const int k0 = c << 6;
        const uint32_t st = smb + (c % 3) * STG;
#pragma unroll
        for (int it = 0; it < 8; it++) {
            const int g   = it * 256 + tid;
            const int arr = it >> 2;
            const int r   = (g >> 3) & 127;
            const int q   = g & 7;
            const half* src = arr ? (B + (size_t)(n0 + r) * ldb + k0 + q * 8)
                                  : (A + (size_t)(m0 + r) * lda + k0 + q * 8);
            const uint32_t dst = st + arr * 16384 + r * 128 + ((q ^ (r & 7)) << 4);
            CPA16(dst, src);
        }
        CPA_COMMIT();
    };

    load_chunk(0);
    if (nch > 1) load_chunk(1);

    for (int c = 0; c < nch; c++) {
        if (c + 1 < nch) CPA_WAIT(1); else CPA_WAIT(0);
        __syncthreads();
        if (c + 2 < nch) load_chunk(c + 2);   // safe: all threads finished chunk c-1

        const uint32_t st = smb + (c % 3) * STG;
        const uint32_t sA = st, sB = st + 16384;

#pragma unroll
        for (int kk = 0; kk < 4; kk++) {
            uint32_t af[4][4], bfr[4][2];
            const int acq = kk * 2 + a_colq_l;
#pragma unroll
            for (int mi = 0; mi < 4; mi++) {
                const int r = wm + mi * 16 + a_row_l;
                LDSM4(af[mi], sA + r * 128 + ((acq ^ (r & 7)) << 4));
            }
            const int bcq = kk * 2 + b_colq_l;
#pragma unroll
            for (int nj = 0; nj < 2; nj++) {
                const int r = wn + nj * 16 + b_row_l;
                uint32_t t4[4];
                LDSM4(t4, sB + r * 128 + ((bcq ^ (r & 7)) << 4));
                bfr[nj*2][0] = t4[0]; bfr[nj*2][1] = t4[1];
                bfr[nj*2+1][0] = t4[2]; bfr[nj*2+1][1] = t4[3];
            }
#pragma unroll
            for (int mi = 0; mi < 4; mi++)
#pragma unroll
                for (int ni = 0; ni < 4; ni++)
                    MMA_F16(acc[mi][ni], af[mi], bfr[ni]);
        }
    }

    const int g = lane >> 2, t = lane & 3;
#pragma unroll
    for (int mi = 0; mi < 4; mi++)
#pragma unroll
        for (int ni = 0; ni < 4; ni++)
#pragma unroll
            for (int h2 = 0; h2 < 2; h2++) {
                const int row = m0 + wm + mi * 16 + g + h2 * 8;
                const int col = n0 + wn + ni * 8 + 2 * t;
                float v0 = acc[mi][ni][h2 * 2 + 0];
                float v1 = acc[mi][ni][h2 * 2 + 1];
                if (resid) {
                    const float* rp = resid + (size_t)row * ldr + col;
                    v0 += rp[0]; v1 += rp[1];
                }
                if (Cf) *(float2*)(Cf + (size_t)row * ldc + col) = make_float2(v0, v1);
                if (Ch)
                    *(uint32_t*)(Ch + (size_t)row * ldc + col) =
                        pack2h(__float2half_rn(v0), __float2half_rn(v1));
            }
}

// ---------------- fp32 -> fp16 convert (4/thread) ----------------
__global__ void cvt4h(const float4* __restrict__ in, uint2* __restrict__ out, long long n4)
{
    long long i = (long long)blockIdx.x * blockDim.x + threadIdx.x;
    if (i >= n4) return;
    float4 v = in[i];
    out[i] = make_uint2(pack2h(__float2half_rn(v.x), __float2half_rn(v.y)),
                        pack2h(__float2half_rn(v.z), __float2half_rn(v.w)));
}

// ---------------- row l2norm -> fp16 ----------------
__global__ void l2norm_rows_h(const float* __restrict__ in, half* __restrict__ out, int cols)
{
    const int row = blockIdx.x;
    const float* x = in + (long long)row * cols;
    float s = 0.f;
    for (int c = threadIdx.x; c < cols; c += blockDim.x) { float v = x[c]; s += v * v; }
    __shared__ float red[32];
#pragma unroll
    for (int o = 16; o; o >>= 1) s += __shfl_xor_sync(0xffffffffu, s, o);
    if ((threadIdx.x & 31) == 0) red[threadIdx.x >> 5] = s;
    __syncthreads();
    const int nw = blockDim.x >> 5;
    if (threadIdx.x < 32) {
        float t = (threadIdx.x < nw) ? red[threadIdx.x] : 0.f;
#pragma unroll
        for (int o = 16; o; o >>= 1) t += __shfl_xor_sync(0xffffffffu, t, o);
        if (threadIdx.x == 0) red[0] = rsqrtf(t);
    }
    __syncthreads();
    const float r = red[0];
    for (int c = threadIdx.x; c < cols; c += blockDim.x)
        out[(long long)row * cols + c] = __float2half_rn(x[c] * r);
}

__global__ void l2norm_rows(const float* __restrict__ in, float* __restrict__ out, int cols)
{
    const int row = blockIdx.x;
    const float* x = in + (long long)row * cols;
    float* y = out + (long long)row * cols;
    float s = 0.f;
    for (int c = threadIdx.x; c < cols; c += blockDim.x) { float v = x[c]; s += v * v; }
    __shared__ float red[32];
#pragma unroll
    for (int o = 16; o; o >>= 1) s += __shfl_xor_sync(0xffffffffu, s, o);
    if ((threadIdx.x & 31) == 0) red[threadIdx.x >> 5] = s;
    __syncthreads();
    const int nw = blockDim.x >> 5;
    if (threadIdx.x < 32) {
        float t = (threadIdx.x < nw) ? red[threadIdx.x] : 0.f;
#pragma unroll
        for (int o = 16; o; o >>= 1) t += __shfl_xor_sync(0xffffffffu, t, o);
        if (threadIdx.x == 0) red[0] = rsqrtf(t);
    }
    __syncthreads();
    const float r = red[0];
    for (int c = threadIdx.x; c < cols; c += blockDim.x) y[c] = x[c] * r;
}

// ---------------- warp-per-head norm + RoPE -> fp16 Q/K ----------------
// grid: SEQ blocks of 256 (8 warps). Warp w handles heads w, w+8, w+16.
// Each lane holds 4 elems (d = i*32+lane); rotate partner is reg i^2 same lane.
__global__ void qk_rope_w(const float* __restrict__ qkv, const float* __restrict__ qknw,
                          const float* __restrict__ cosb, const float* __restrict__ sinb,
                          half* __restrict__ Q, half* __restrict__ Kb)
{
    const int s    = blockIdx.x;
    const int lane = threadIdx.x & 31;
    const int warp = threadIdx.x >> 5;

#pragma unroll
    for (int hi = 0; hi < 3; hi++) {
        const int h = warp + hi * 8;
        const float* src = qkv + (size_t)s * QKVO + h * HD;
        float v[4];
        float ss = 0.f;
#pragma unroll
        for (int i = 0; i < 4; i++) {
            v[i] = src[i * 32 + lane];
            ss += v[i] * v[i];
        }
#pragma unroll
        for (int o = 16; o; o >>= 1) ss += __shfl_xor_sync(0xffffffffu, ss, o);
        const float r = rsqrtf(ss);
        float nv[4];
#pragma unroll
        for (int i = 0; i < 4; i++)
            nv[i] = v[i] * r * qknw[h * HD + i * 32 + lane];
        half ov[4];
#pragma unroll
        for (int i = 0; i < 4; i++) {
            const int d = i * 32 + lane;
            const float rot = nv[i ^ 2];           // d±64 partner
            ov[i] = __float2half_rn(nv[i] * cosb[s * HD + d] + rot * sinb[s * HD + d]);
        }
        half* dst = (h < NH) ? (Q + ((size_t)h * SEQ + s) * HD)
                             : (Kb + ((size_t)(h - NH) * SEQ + s) * HD);
#pragma unroll
        for (int i = 0; i < 4; i++) dst[i * 32 + lane] = ov[i];
    }
}

// ---------------- V transpose -> fp16 ----------------
__global__ void v_transpose_h(const float* __restrict__ qkv, half* __restrict__ Vt)
{
    __shared__ float t[32][33];
    const int h = blockIdx.z;
    const int s0 = blockIdx.x * 32;
    const int d0 = blockIdx.y * 32;
    t[threadIdx.y][threadIdx.x] =
        qkv[(long long)(s0 + threadIdx.y) * QKVO + QKH * HD + h * HD + d0 + threadIdx.x];
    __syncthreads();
    Vt[((size_t)h * HD + d0 + threadIdx.y) * SEQ + s0 + threadIdx.x] =
        __float2half_rn(t[threadIdx.x][threadIdx.y]);
}

// ---------------- causal softmax (fp16 in, fp16 out, K-limited) ----------------
__global__ void softmax_causal_h(const half* __restrict__ scores, const float* __restrict__ maskp,
                                 half* __restrict__ P)
{
    const int q = blockIdx.x;
    const int h = blockIdx.y;
    const int kmax = ((q >> 7) + 1) << 7;
    const half* row = scores + ((size_t)h * SEQ + q) * SEQ;
    const float mpen = -128.f * maskp[0];
    const int tid = threadIdx.x;

    float vals[4];
    float mx = -1e30f;
#pragma unroll
    for (int i = 0; i < 4; i++) {
        int k = tid + i * 256;
        if (k < kmax) {
            float v = __half2float(row[k]) + (k > q ? mpen : 0.f);
            vals[i] = v;
            mx = fmaxf(mx, v);
        } else vals[i] = -1e30f;
    }
    __shared__ float redm[8];
    __shared__ float reds[8];
#pragma unroll
    for (int o = 16; o; o >>= 1) mx = fmaxf(mx, __shfl_xor_sync(0xffffffffu, mx, o));
    if ((tid & 31) == 0) redm[tid >> 5] = mx;
    __syncthreads();
    if (tid < 32) {
        float m2 = (tid < 8) ? redm[tid] : -1e30f;
#pragma unroll
        for (int o = 16; o; o >>= 1) m2 = fmaxf(m2, __shfl_xor_sync(0xffffffffu, m2, o));
        if (tid == 0) redm[0] = m2;
    }
    __syncthreads();
    mx = redm[0];

    float s = 0.f;
#pragma unroll
    for (int i = 0; i < 4; i++) {
        int k = tid + i * 256;
        if (k < kmax) { vals[i] = expf(vals[i] - mx); s += vals[i]; }
    }
#pragma unroll
    for (int o = 16; o; o >>= 1) s += __shfl_xor_sync(0xffffffffu, s, o);
    if ((tid & 31) == 0) reds[tid >> 5] = s;
    __syncthreads();
    if (tid < 32) {
        float t2 = (tid < 8) ? reds[tid] : 0.f;
#pragma unroll
        for (int o = 16; o; o >>= 1) t2 += __shfl_xor_sync(0xffffffffu, t2, o);
        if (tid == 0) reds[0] = 1.f / t2;
    }
    __syncthreads();
    const float inv = reds[0];
    const size_t base = ((size_t)h * SEQ + q) * SEQ;
#pragma unroll
    for (int i = 0; i < 4; i++) {
        int k = tid + i * 256;
        if (k < kmax) P[base + k] = __float2half_rn(vals[i] * inv);
    }
}

// ---------------- SwiGLU -> fp16 (vectorized 4-wide) ----------------
__global__ void silu_mul_h4(const float4* __restrict__ gu, uint2* __restrict__ act, int n4row)
{
    const long long i = (long long)blockIdx.x * blockDim.x + threadIdx.x;   // over SEQ*DFF/4
    const int s  = (int)(i / n4row);
    const int f4 = (int)(i % n4row);
    const float4 g = gu[(size_t)s * (2 * n4row) + f4];
    const float4 u = gu[(size_t)s * (2 * n4row) + n4row + f4];
    float r0 = (g.x / (1.f + expf(-g.x))) * u.x;
    float r1 = (g.y / (1.f + expf(-g.y))) * u.y;
    float r2 = (g.z / (1.f + expf(-g.z))) * u.z;
    float r3 = (g.w / (1.f + expf(-g.w))) * u.w;
    act[i] = make_uint2(pack2h(__float2half_rn(r0), __float2half_rn(r1)),
                        pack2h(__float2half_rn(r2), __float2half_rn(r3)));
}

// ---------------- lm_head GEMV (fp32) ----------------
__global__ void lm_head(const float* __restrict__ last, const float* __restrict__ W,
                        float* __restrict__ out)
{
    const int warp = threadIdx.x >> 5;
    const int lane = threadIdx.x & 31;
    const int v = blockIdx.x * 8 + warp;
    const float* w = W + (long long)v * HDIM;
    float s = 0.f;
#pragma unroll
    for (int j = lane * 4; j < HDIM; j += 128) {
        float4 wv = *(const float4*)(w + j);
        float4 lv = *(const float4*)(last + j);
        s += wv.x * lv.x + wv.y * lv.y + wv.z * lv.z + wv.w * lv.w;
    }
#pragma unroll
    for (int o = 16; o; o >>= 1) s += __shfl_xor_sync(0xffffffffu, s, o);
    if (lane == 0) out[v] = s;
}

// ---------------- launcher ----------------
extern "C" void kernel_launch(void* const* d_in, const int* in_sizes, int n_in,
                              void* d_out, int out_size)
{
    const float* hidden = (const float*)d_in[0];
    const float* qkv_w  = (const float*)d_in[1];
    const float* qknw   = (const float*)d_in[2];
    const float* o_w    = (const float*)d_in[3];
    const float* gu_w   = (const float*)d_in[4];
    const float* dn_w   = (const float*)d_in[5];
    const float* lm_w   = (const float*)d_in[6];
    const float* cosb   = (const float*)d_in[7];
    const float* sinb   = (const float*)d_in[8];
    const float* maskp  = (const float*)d_in[9];
    float* outp = (float*)d_out;

    const int SMB = 3 * 32768 + 1024;   // 99328 -> 2 CTAs/SM
    cudaFuncSetAttribute(hgemm, cudaFuncAttributeMaxDynamicSharedMemorySize, SMB);

    float *px, *pqkv, *pgu, *plast;
    half *phnf, *pwhf, *pqf, *pkf, *pvtf, *pscf, *ppf, *ppaof, *pactf;
    cudaGetSymbolAddress((void**)&px,    g_x);
    cudaGetSymbolAddress((void**)&phnf,  g_hnf);
    cudaGetSymbolAddress((void**)&pwhf,  g_whf);
    cudaGetSymbolAddress((void**)&pqkv,  g_qkv);
    cudaGetSymbolAddress((void**)&pqf,   g_qf);
    cudaGetSymbolAddress((void**)&pkf,   g_kf);
    cudaGetSymbolAddress((void**)&pvtf,  g_vtf);
    cudaGetSymbolAddress((void**)&pscf,  g_scf);
    cudaGetSymbolAddress((void**)&ppf,   g_pf);
    cudaGetSymbolAddress((void**)&ppaof, g_paof);
    cudaGetSymbolAddress((void**)&pgu,   g_gu);
    cudaGetSymbolAddress((void**)&pactf, g_actf);
    cudaGetSymbolAddress((void**)&plast, g_last);

    const float* xin = hidden;

    for (int l = 0; l < NLAY; l++) {
        l2norm_rows_h<<<SEQ, 256>>>(xin, phnf, HDIM);

        // QKV projection
        {
            long long n4 = (long long)QKVO * HDIM / 4;
            cvt4h<<<(unsigned)((n4 + 255) / 256), 256>>>(
                (const float4*)(qkv_w + (long long)l * QKVO * HDIM), (uint2*)pwhf, n4);
        }
        hgemm<<<dim3(SEQ / 128, QKVO / 128, 1), 256, SMB>>>(
            phnf, HDIM, pwhf, HDIM, pqkv, nullptr, QKVO, HDIM,
            nullptr, 0, 0, 0, 0, 0, 0);

        qk_rope_w<<<SEQ, 256>>>(pqkv, qknw + (long long)l * QKH * HD, cosb, sinb, pqf, pkf);
        v_transpose_h<<<dim3(SEQ / 32, HD / 32, KVH), dim3(32, 32)>>>(pqkv, pvtf);

        // scores = Q K^T per head -> fp16 (causal tile skip)
        hgemm<<<dim3(SEQ / 128, SEQ / 128, NH), 256, SMB>>>(
            pqf, HD, pkf, HD, nullptr, pscf, SEQ, HD,
            nullptr, 0,
            (long long)SEQ * HD, (long long)SEQ * HD, (long long)SEQ * SEQ, 1, 1);

        softmax_causal_h<<<dim3(SEQ, NH), 256>>>(pscf, maskp, ppf);

        // out = P V (K-limited; fp16 output slab per head)
        hgemm<<<dim3(SEQ / 128, 1, NH), 256, SMB>>>(
            ppf, SEQ, pvtf, SEQ, nullptr, ppaof, HDIM, SEQ,
            nullptr, 0,
            (long long)SEQ * SEQ, (long long)HD * SEQ, (long long)HD, 1, 2);

        // O projection + residual
        {
            long long n4 = (long long)HDIM * HDIM / 4;
            cvt4h<<<(unsigned)((n4 + 255) / 256), 256>>>(
                (const float4*)(o_w + (long long)l * HDIM * HDIM), (uint2*)pwhf, n4);
        }
        hgemm<<<dim3(SEQ / 128, HDIM / 128, 1), 256, SMB>>>(
            ppaof, HDIM, pwhf, HDIM, px, nullptr, HDIM, HDIM,
            xin, HDIM, 0, 0, 0, 0, 0);

        // MLP
        l2norm_rows_h<<<SEQ, 256>>>(px, phnf, HDIM);
        {
            long long n4 = (long long)2 * DFF * HDIM / 4;
            cvt4h<<<(unsigned)((n4 + 255) / 256), 256>>>(
                (const float4*)(gu_w + (long long)l * 2 * DFF * HDIM), (uint2*)pwhf, n4);
        }
        hgemm<<<dim3(SEQ / 128, 2 * DFF / 128, 1), 256, SMB>>>(
            phnf, HDIM, pwhf, HDIM, pgu, nullptr, 2 * DFF, HDIM,
            nullptr, 0, 0, 0, 0, 0, 0);
        silu_mul_h4<<<(SEQ * DFF / 4) / 256, 256>>>((const float4*)pgu, (uint2*)pactf, DFF / 4);
        {
            long long n4 = (long long)HDIM * DFF / 4;
            cvt4h<<<(unsigned)((n4 + 255) / 256), 256>>>(
                (const float4*)(dn_w + (long long)l * HDIM * DFF), (uint2*)pwhf, n4);
        }
        hgemm<<<dim3(SEQ / 128, HDIM / 128, 1), 256, SMB>>>(
            pactf, DFF, pwhf, DFF, px, nullptr, HDIM, DFF,
            px, HDIM, 0, 0, 0, 0, 0);

        xin = px;
    }

    l2norm_rows<<<1, 256>>>(px + (long long)(SEQ - 1) * HDIM, plast, HDIM);
    lm_head<<<VOC / 8, 256>>>(plast, lm_w, outp);
}